// round 5
// baseline (speedup 1.0000x reference)
#include <cuda_runtime.h>

typedef unsigned long long u64;

#define NSMAX 131072
__device__ float g_p2[54 * NSMAX];    // conv output  [k][sample]
__device__ float g_h [128 * NSMAX];   // fc1 output   [k][sample]

__device__ __forceinline__ u64 dup2(float a) {
    u64 r; asm("mov.b64 %0, {%1, %1};" : "=l"(r) : "r"(__float_as_uint(a))); return r;
}
__device__ __forceinline__ u64 pack2(float lo, float hi) {
    u64 r; asm("mov.b64 %0, {%1, %2};" : "=l"(r) : "r"(__float_as_uint(lo)), "r"(__float_as_uint(hi))); return r;
}
__device__ __forceinline__ void fma2(u64& acc, u64 a, u64 b) {
    asm("fma.rn.f32x2 %0, %1, %2, %0;" : "+l"(acc) : "l"(a), "l"(b));
}
__device__ __forceinline__ float2 unpack2(u64 v) {
    unsigned lo, hi; asm("mov.b64 {%0, %1}, %2;" : "=r"(lo), "=r"(hi) : "l"(v));
    return make_float2(__uint_as_float(lo), __uint_as_float(hi));
}
__device__ __forceinline__ u64 relu2(u64 v) {
    float2 f = unpack2(v);
    return pack2(fmaxf(f.x, 0.0f), fmaxf(f.y, 0.0f));
}

// ================================================================
// Kernel 1: conv1+pool+relu+conv2+pool+relu -> g_p2[k][s]
// c1p staged through smem (per-lane column, conflict-free) to avoid spills
// ================================================================
#define CTPB 128
#define CONV_SM_FLOATS (208 + 108 * 128)
#define CONV_SM_BYTES (CONV_SM_FLOATS * 4)
// header: c1w[0..26] c1b[27..29] c2w[30..191] c2b[192..197]
#define C1S(ch, y, xx) sm[208 + (((ch) * 6 + (y)) * 6 + (xx)) * 128 + tid]

__global__ void __launch_bounds__(CTPB, 3)
conv_kernel(const float* __restrict__ x,
            const float* __restrict__ c1w, const float* __restrict__ c1b,
            const float* __restrict__ c2w, const float* __restrict__ c2b,
            int nsamp)
{
    extern __shared__ float sm[];
    const int tid = threadIdx.x;
    // NOTE: strided loops — CTPB=128 is smaller than some sizes (c2w=162)!
    for (int i = tid; i < 27;  i += CTPB) sm[i]       = c1w[i];
    for (int i = tid; i < 3;   i += CTPB) sm[27 + i]  = c1b[i];
    for (int i = tid; i < 162; i += CTPB) sm[30 + i]  = c2w[i];
    for (int i = tid; i < 6;   i += CTPB) sm[192 + i] = c2b[i];
    __syncthreads();

    const long long sample = (long long)blockIdx.x * CTPB + tid;
    if (sample >= nsamp) return;
    const float* xp = x + sample * 128;

    // ---- conv1 (1->3, 3x3 pad1 on 12x12) + maxpool2 + relu -> C1S in smem ----
#pragma unroll
    for (int py = 0; py < 6; py++) {
        float ra[4][12];
#pragma unroll
        for (int j = 0; j < 4; j++) {
            const int r = 2 * py - 1 + j;
            if (r < 0 || r >= 11) {
#pragma unroll
                for (int c = 0; c < 12; c++) ra[j][c] = 0.0f;
            } else if (r == 10) {
#pragma unroll
                for (int c = 0; c < 8; c += 2) {
                    float2 v = *(const float2*)(xp + 120 + c);
                    ra[j][c] = v.x; ra[j][c + 1] = v.y;
                }
                ra[j][8] = 0.0f; ra[j][9] = 0.0f; ra[j][10] = 0.0f; ra[j][11] = 0.0f;
            } else {
#pragma unroll
                for (int c = 0; c < 12; c += 2) {
                    float2 v = *(const float2*)(xp + 12 * r + c);
                    ra[j][c] = v.x; ra[j][c + 1] = v.y;
                }
            }
        }
        u64 pr[3][12];
#pragma unroll
        for (int j = 0; j < 3; j++)
#pragma unroll
            for (int ix = 0; ix < 12; ix++)
                pr[j][ix] = pack2(ra[j][ix], ra[j + 1][ix]);

#pragma unroll
        for (int oc = 0; oc < 3; oc++) {
#pragma unroll
            for (int px = 0; px < 6; px++) {
                u64 a0 = 0ull, a1 = 0ull;
#pragma unroll
                for (int ky = 0; ky < 3; ky++) {
#pragma unroll
                    for (int kx = 0; kx < 3; kx++) {
                        const u64 wd = dup2(sm[oc * 9 + ky * 3 + kx]);
                        const int ix0 = 2 * px + kx - 1;
                        const int ix1 = 2 * px + kx;
                        if (ix0 >= 0 && ix0 < 12) fma2(a0, wd, pr[ky][ix0]);
                        if (ix1 < 12)             fma2(a1, wd, pr[ky][ix1]);
                    }
                }
                float2 v0 = unpack2(a0), v1 = unpack2(a1);
                float m = fmaxf(fmaxf(v0.x, v0.y), fmaxf(v1.x, v1.y));
                C1S(oc, py, px) = fmaxf(m + sm[27 + oc], 0.0f);
            }
        }
    }

    // ---- conv2 (3->6, 3x3 pad1 on 6x6) + maxpool2 + relu -> g_p2[k][s] ----
#pragma unroll
    for (int py = 0; py < 3; py++) {
        u64 acc[6][3][2];
#pragma unroll
        for (int oc = 0; oc < 6; oc++)
#pragma unroll
            for (int px = 0; px < 3; px++) { acc[oc][px][0] = 0ull; acc[oc][px][1] = 0ull; }

#pragma unroll
        for (int ic = 0; ic < 3; ic++) {
            u64 pc[3][6];
#pragma unroll
            for (int j = 0; j < 3; j++) {
                const int iy0 = 2 * py - 1 + j;
                const int iy1 = 2 * py + j;
#pragma unroll
                for (int ix = 0; ix < 6; ix++) {
                    const float lo = (iy0 >= 0 && iy0 < 6) ? C1S(ic, iy0, ix) : 0.0f;
                    const float hi = (iy1 < 6) ? C1S(ic, iy1, ix) : 0.0f;
                    pc[j][ix] = pack2(lo, hi);
                }
            }
#pragma unroll
            for (int oc = 0; oc < 6; oc++) {
#pragma unroll
                for (int ky = 0; ky < 3; ky++) {
#pragma unroll
                    for (int kx = 0; kx < 3; kx++) {
                        const u64 wd = dup2(sm[30 + oc * 27 + ic * 9 + ky * 3 + kx]);
#pragma unroll
                        for (int px = 0; px < 3; px++) {
                            const int ix0 = 2 * px + kx - 1;
                            const int ix1 = 2 * px + kx;
                            if (ix0 >= 0 && ix0 < 6) fma2(acc[oc][px][0], wd, pc[ky][ix0]);
                            if (ix1 < 6)             fma2(acc[oc][px][1], wd, pc[ky][ix1]);
                        }
                    }
                }
            }
        }
#pragma unroll
        for (int oc = 0; oc < 6; oc++) {
            const float bb = sm[192 + oc];
#pragma unroll
            for (int px = 0; px < 3; px++) {
                float2 v0 = unpack2(acc[oc][px][0]), v1 = unpack2(acc[oc][px][1]);
                float m = fmaxf(fmaxf(v0.x, v0.y), fmaxf(v1.x, v1.y));
                g_p2[(long long)(oc * 9 + py * 3 + px) * NSMAX + sample] = fmaxf(m + bb, 0.0f);
            }
        }
    }
}

// ================================================================
// Kernel 2: fc1 (54->128)+relu -> g_h[k][s]
// 256 thr, block tile 256 samples; thread tile 16 samp x 8 out
// ================================================================
#define F1TPB 256
#define F1_OFF_W1D 0                       // 54*128 u64 = 13824 floats
#define F1_OFF_B1D 13824                   // 128 u64 = 256 floats
#define F1_OFF_A   14080                   // [54][264]
#define F1_AS      264
#define F1_SM_FLOATS (14080 + 54 * 264)
#define F1_SM_BYTES (F1_SM_FLOATS * 4)

__global__ void __launch_bounds__(F1TPB, 1)
fc1_kernel(const float* __restrict__ w1, const float* __restrict__ b1, int nsamp)
{
    extern __shared__ float sm[];
    const int tid = threadIdx.x;
    const long long base = (long long)blockIdx.x * 256;

    for (int i = tid; i < 6912; i += F1TPB) {
        const int k = i / 128, o = i & 127;
        ((u64*)(sm + F1_OFF_W1D))[k * 128 + o] = dup2(w1[o * 54 + k]);
    }
    for (int i = tid; i < 128; i += F1TPB) ((u64*)(sm + F1_OFF_B1D))[i] = dup2(b1[i]);
    for (int i = tid; i < 54 * 64; i += F1TPB) {
        const int k = i >> 6, s4 = (i & 63) * 4;
        const float4 v = *(const float4*)(g_p2 + (long long)k * NSMAX + base + s4);
        *(float4*)(sm + F1_OFF_A + k * F1_AS + s4) = v;
    }
    __syncthreads();

    const int sgrp = tid & 15;     // 16 sample groups of 16
    const int ogrp = tid >> 4;     // 16 output groups of 8
    const int s0 = sgrp * 16;
    const int o0 = ogrp * 8;

    u64 acc[8][8];                 // [o][sample-pair]
    {
        const u64* bp = (const u64*)(sm + F1_OFF_B1D) + o0;
#pragma unroll
        for (int o = 0; o < 8; o++) {
            const u64 b = bp[o];
#pragma unroll
            for (int sp = 0; sp < 8; sp++) acc[o][sp] = b;
        }
    }
    {
        const float* ap = sm + F1_OFF_A + s0;
        const u64* wp = (const u64*)(sm + F1_OFF_W1D) + o0;
#pragma unroll 2
        for (int k = 0; k < 54; k++) {
            ulonglong2 a01 = *(const ulonglong2*)ap;
            ulonglong2 a23 = *(const ulonglong2*)(ap + 4);
            ulonglong2 a45 = *(const ulonglong2*)(ap + 8);
            ulonglong2 a67 = *(const ulonglong2*)(ap + 12);
            ulonglong2 w01 = *(const ulonglong2*)wp;
            ulonglong2 w23 = *(const ulonglong2*)(wp + 2);
            ulonglong2 w45 = *(const ulonglong2*)(wp + 4);
            ulonglong2 w67 = *(const ulonglong2*)(wp + 6);
            u64 av[8] = {a01.x, a01.y, a23.x, a23.y, a45.x, a45.y, a67.x, a67.y};
            u64 wv[8] = {w01.x, w01.y, w23.x, w23.y, w45.x, w45.y, w67.x, w67.y};
#pragma unroll
            for (int o = 0; o < 8; o++)
#pragma unroll
                for (int sp = 0; sp < 8; sp++)
                    fma2(acc[o][sp], av[sp], wv[o]);
            ap += F1_AS; wp += 128;
        }
    }
#pragma unroll
    for (int o = 0; o < 8; o++) {
        u64* gh = (u64*)(g_h + ((long long)(o0 + o) * NSMAX + base + s0));
#pragma unroll
        for (int j = 0; j < 4; j++) {
            ulonglong2 v;
            v.x = relu2(acc[o][2 * j]);
            v.y = relu2(acc[o][2 * j + 1]);
            *(ulonglong2*)(gh + 2 * j) = v;
        }
    }
}

// ================================================================
// Kernel 3: out (128->128) -> d_out
// 256 thr, block tile 256 samples; thread tile 8 samp x 16 out
// ================================================================
#define OTPB 256
#define O_OFF_W2T 0                        // [k][o] 128*128 = 16384
#define O_OFF_B2  16384                    // 128
#define O_OFF_H   16512                    // [128][264]
#define O_HS      264
#define O_SM_FLOATS (16512 + 128 * 264)
#define O_SM_BYTES (O_SM_FLOATS * 4)

__global__ void __launch_bounds__(OTPB, 1)
out_kernel(const float* __restrict__ w2, const float* __restrict__ b2,
           float* __restrict__ out, int nsamp)
{
    extern __shared__ float sm[];
    const int tid = threadIdx.x;
    const long long base = (long long)blockIdx.x * 256;

    for (int i = tid; i < 16384; i += OTPB) {
        const int k = i >> 7, o = i & 127;
        sm[O_OFF_W2T + k * 128 + o] = w2[o * 128 + k];
    }
    for (int i = tid; i < 128; i += OTPB) sm[O_OFF_B2 + i] = b2[i];
    for (int i = tid; i < 128 * 64; i += OTPB) {
        const int k = i >> 6, s4 = (i & 63) * 4;
        const float4 v = *(const float4*)(g_h + (long long)k * NSMAX + base + s4);
        *(float4*)(sm + O_OFF_H + k * O_HS + s4) = v;
    }
    __syncthreads();

    const int ogrp = tid & 7;      // 8 output groups of 16
    const int sgrp = tid >> 3;     // 32 sample groups of 8
    const int o0 = ogrp * 16;
    const int s0 = sgrp * 8;

    u64 acc[8][8];                 // [s][output-pair]
    {
        const u64* bp = (const u64*)(sm + O_OFF_B2) + (o0 >> 1);
        u64 b[8];
#pragma unroll
        for (int j = 0; j < 8; j++) b[j] = bp[j];
#pragma unroll
        for (int s = 0; s < 8; s++)
#pragma unroll
            for (int j = 0; j < 8; j++) acc[s][j] = b[j];
    }
    {
        const float* hp = sm + O_OFF_H + s0;
        const float* wp = sm + O_OFF_W2T + o0;
#pragma unroll 2
        for (int k = 0; k < 128; k++) {
            const float4 h0 = *(const float4*)hp;
            const float4 h1 = *(const float4*)(hp + 4);
            const ulonglong2 wA = *(const ulonglong2*)wp;
            const ulonglong2 wB = *(const ulonglong2*)(wp + 4);
            const ulonglong2 wC = *(const ulonglong2*)(wp + 8);
            const ulonglong2 wD = *(const ulonglong2*)(wp + 12);
            u64 hd[8];
            hd[0] = dup2(h0.x); hd[1] = dup2(h0.y); hd[2] = dup2(h0.z); hd[3] = dup2(h0.w);
            hd[4] = dup2(h1.x); hd[5] = dup2(h1.y); hd[6] = dup2(h1.z); hd[7] = dup2(h1.w);
            u64 wv[8] = {wA.x, wA.y, wB.x, wB.y, wC.x, wC.y, wD.x, wD.y};
#pragma unroll
            for (int s = 0; s < 8; s++)
#pragma unroll
                for (int j = 0; j < 8; j++)
                    fma2(acc[s][j], hd[s], wv[j]);
            hp += O_HS; wp += 128;
        }
    }
#pragma unroll
    for (int s = 0; s < 8; s++) {
        const long long gs = base + s0 + s;
        if (gs < nsamp) {
            u64* op = (u64*)(out + gs * 128 + o0);
#pragma unroll
            for (int j = 0; j < 4; j++) {
                ulonglong2 v; v.x = acc[s][2 * j]; v.y = acc[s][2 * j + 1];
                *(ulonglong2*)(op + 2 * j) = v;
            }
        }
    }
}

extern "C" void kernel_launch(void* const* d_in, const int* in_sizes, int n_in,
                              void* d_out, int out_size)
{
    const float* x   = (const float*)d_in[0];
    const float* c1w = (const float*)d_in[1];
    const float* c1b = (const float*)d_in[2];
    const float* c2w = (const float*)d_in[3];
    const float* c2b = (const float*)d_in[4];
    const float* w1  = (const float*)d_in[5];
    const float* b1  = (const float*)d_in[6];
    const float* w2  = (const float*)d_in[7];
    const float* b2  = (const float*)d_in[8];
    float* out = (float*)d_out;

    const int nsamp = in_sizes[0] / 128;

    cudaFuncSetAttribute(conv_kernel, cudaFuncAttributeMaxDynamicSharedMemorySize, CONV_SM_BYTES);
    cudaFuncSetAttribute(fc1_kernel,  cudaFuncAttributeMaxDynamicSharedMemorySize, F1_SM_BYTES);
    cudaFuncSetAttribute(out_kernel,  cudaFuncAttributeMaxDynamicSharedMemorySize, O_SM_BYTES);

    conv_kernel<<<(nsamp + CTPB - 1) / CTPB, CTPB, CONV_SM_BYTES>>>(x, c1w, c1b, c2w, c2b, nsamp);

    const int gblocks = (nsamp + 255) / 256;
    fc1_kernel<<<gblocks, F1TPB, F1_SM_BYTES>>>(w1, b1, nsamp);
    out_kernel<<<gblocks, OTPB, O_SM_BYTES>>>(w2, b2, out, nsamp);
}

// round 6
// speedup vs baseline: 1.4162x; 1.4162x over previous
#include <cuda_runtime.h>

typedef unsigned long long u64;

#define NSMAX 131072
__device__ float g_c1[108 * NSMAX];   // conv1+pool output [ch*36+y*6+x][sample]
__device__ float g_p2[54 * NSMAX];    // conv2+pool output [k][sample]
__device__ float g_h [NSMAX * 128];   // fc1 output [sample][o]

__device__ __forceinline__ u64 dup2(float a) {
    u64 r; asm("mov.b64 %0, {%1, %1};" : "=l"(r) : "r"(__float_as_uint(a))); return r;
}
__device__ __forceinline__ u64 pack2(float lo, float hi) {
    u64 r; asm("mov.b64 %0, {%1, %2};" : "=l"(r) : "r"(__float_as_uint(lo)), "r"(__float_as_uint(hi))); return r;
}
__device__ __forceinline__ void fma2(u64& acc, u64 a, u64 b) {
    asm("fma.rn.f32x2 %0, %1, %2, %0;" : "+l"(acc) : "l"(a), "l"(b));
}
__device__ __forceinline__ float2 unpack2(u64 v) {
    unsigned lo, hi; asm("mov.b64 {%0, %1}, %2;" : "=r"(lo), "=r"(hi) : "l"(v));
    return make_float2(__uint_as_float(lo), __uint_as_float(hi));
}

// ================================================================
// Kernel A1: conv1 (1->3, 3x3 pad1, 12x12) + maxpool2 + relu -> g_c1
// thread per sample; weights in REGISTERS; scalar fma; ~110 regs
// ================================================================
#define A1TPB 256
__global__ void __launch_bounds__(A1TPB)
conv1_kernel(const float* __restrict__ x,
             const float* __restrict__ c1w, const float* __restrict__ c1b, int nsamp)
{
    __shared__ float ws[32];
    const int tid = threadIdx.x;
    if (tid < 27) ws[tid] = c1w[tid];
    if (tid < 3)  ws[27 + tid] = c1b[tid];
    __syncthreads();

    const long long s = (long long)blockIdx.x * A1TPB + tid;
    if (s >= nsamp) return;
    const float* xp = x + s * 128;

    float W[27];
#pragma unroll
    for (int i = 0; i < 27; i++) W[i] = ws[i];
    const float B0 = ws[27], B1 = ws[28], B2 = ws[29];

#pragma unroll
    for (int py = 0; py < 6; py++) {
        float r[4][12];
#pragma unroll
        for (int j = 0; j < 4; j++) {
            const int rr = 2 * py - 1 + j;
            if (rr < 0 || rr >= 11) {
#pragma unroll
                for (int c = 0; c < 12; c++) r[j][c] = 0.0f;
            } else if (rr == 10) {
#pragma unroll
                for (int c = 0; c < 8; c += 2) {
                    float2 v = *(const float2*)(xp + 120 + c);
                    r[j][c] = v.x; r[j][c + 1] = v.y;
                }
                r[j][8] = 0.0f; r[j][9] = 0.0f; r[j][10] = 0.0f; r[j][11] = 0.0f;
            } else {
#pragma unroll
                for (int c = 0; c < 12; c += 2) {
                    float2 v = *(const float2*)(xp + 12 * rr + c);
                    r[j][c] = v.x; r[j][c + 1] = v.y;
                }
            }
        }
#pragma unroll
        for (int oc = 0; oc < 3; oc++) {
            float v0[12], v1[12];
#pragma unroll
            for (int cx = 0; cx < 12; cx++) {
                float a0 = 0.0f, a1 = 0.0f;
#pragma unroll
                for (int ky = 0; ky < 3; ky++) {
#pragma unroll
                    for (int kx = 0; kx < 3; kx++) {
                        const int col = cx + kx - 1;
                        if (col >= 0 && col < 12) {
                            const float w = W[oc * 9 + ky * 3 + kx];
                            a0 = fmaf(w, r[ky][col],     a0);   // out row 2py
                            a1 = fmaf(w, r[ky + 1][col], a1);   // out row 2py+1
                        }
                    }
                }
                v0[cx] = a0; v1[cx] = a1;
            }
            const float bb = (oc == 0) ? B0 : ((oc == 1) ? B1 : B2);
#pragma unroll
            for (int px = 0; px < 6; px++) {
                float m = fmaxf(fmaxf(v0[2 * px], v0[2 * px + 1]),
                                fmaxf(v1[2 * px], v1[2 * px + 1]));
                g_c1[(long long)(oc * 36 + py * 6 + px) * NSMAX + s] = fmaxf(m + bb, 0.0f);
            }
        }
    }
}

// ================================================================
// Kernel A2: conv2 (3->6, 3x3 pad1, 6x6) + maxpool2 + relu -> g_p2
// thread per sample; oc processed in halves of 3 to bound registers
// ================================================================
#define A2TPB 256
__global__ void __launch_bounds__(A2TPB)
conv2_kernel(const float* __restrict__ c2w, const float* __restrict__ c2b, int nsamp)
{
    __shared__ float ws[168];
    const int tid = threadIdx.x;
    if (tid < 162) ws[tid] = c2w[tid];
    if (tid < 6)   ws[162 + tid] = c2b[tid];
    __syncthreads();

    const long long s = (long long)blockIdx.x * A2TPB + tid;
    if (s >= nsamp) return;

#pragma unroll
    for (int py = 0; py < 3; py++) {
#pragma unroll
        for (int oh = 0; oh < 2; oh++) {
            u64 acc[3][3][2];   // [oc-in-half][px][dx]
#pragma unroll
            for (int q = 0; q < 3; q++)
#pragma unroll
                for (int px = 0; px < 3; px++) { acc[q][px][0] = 0ull; acc[q][px][1] = 0ull; }

#pragma unroll
            for (int ic = 0; ic < 3; ic++) {
                float rw[4][6];
#pragma unroll
                for (int j = 0; j < 4; j++) {
                    const int y = 2 * py - 1 + j;
                    if (y < 0 || y > 5) {
#pragma unroll
                        for (int ix = 0; ix < 6; ix++) rw[j][ix] = 0.0f;
                    } else {
#pragma unroll
                        for (int ix = 0; ix < 6; ix++)
                            rw[j][ix] = g_c1[(long long)(ic * 36 + y * 6 + ix) * NSMAX + s];
                    }
                }
                u64 pc[3][6];
#pragma unroll
                for (int j = 0; j < 3; j++)
#pragma unroll
                    for (int ix = 0; ix < 6; ix++)
                        pc[j][ix] = pack2(rw[j][ix], rw[j + 1][ix]);

#pragma unroll
                for (int q = 0; q < 3; q++) {
                    const int oc = oh * 3 + q;
#pragma unroll
                    for (int ky = 0; ky < 3; ky++) {
#pragma unroll
                        for (int kx = 0; kx < 3; kx++) {
                            const u64 wd = dup2(ws[oc * 27 + ic * 9 + ky * 3 + kx]);
#pragma unroll
                            for (int px = 0; px < 3; px++) {
                                const int ix0 = 2 * px + kx - 1;
                                const int ix1 = 2 * px + kx;
                                if (ix0 >= 0 && ix0 < 6) fma2(acc[q][px][0], wd, pc[ky][ix0]);
                                if (ix1 < 6)             fma2(acc[q][px][1], wd, pc[ky][ix1]);
                            }
                        }
                    }
                }
            }
#pragma unroll
            for (int q = 0; q < 3; q++) {
                const int oc = oh * 3 + q;
                const float bb = ws[162 + oc];
#pragma unroll
                for (int px = 0; px < 3; px++) {
                    float2 v0 = unpack2(acc[q][px][0]), v1 = unpack2(acc[q][px][1]);
                    float m = fmaxf(fmaxf(v0.x, v0.y), fmaxf(v1.x, v1.y));
                    g_p2[(long long)(oc * 9 + py * 3 + px) * NSMAX + s] = fmaxf(m + bb, 0.0f);
                }
            }
        }
    }
}

// ================================================================
// Kernel B: fc1 (54->128) + relu -> g_h[s][o]
// 256 thr / 256 samples; tile 8 samp x 16 out; 6 LDS.128 / 64 fma2
// ================================================================
#define BTPB 256
#define B_W1   0                         // [54][132]  w1t[k*132+o]
#define B_B1   7128                      // 128
#define B_A    7256                      // [54][260]  a[k*260+s]
#define B_AS   260
#define B_SM_FLOATS (7256 + 54 * 260)    // 21296 -> 85.2KB
#define B_SM_BYTES (B_SM_FLOATS * 4)

__global__ void __launch_bounds__(BTPB)
fc1_kernel(const float* __restrict__ w1, const float* __restrict__ b1, int nsamp)
{
    extern __shared__ float sm[];
    const int tid = threadIdx.x;
    const long long base = (long long)blockIdx.x * 256;

    for (int i = tid; i < 6912; i += BTPB) {
        const int o = i / 54, k = i - o * 54;       // coalesced w1 read
        sm[B_W1 + k * 132 + o] = w1[i];
    }
    for (int i = tid; i < 128; i += BTPB) sm[B_B1 + i] = b1[i];
    for (int i = tid; i < 54 * 64; i += BTPB) {
        const int k = i >> 6, s4 = (i & 63) * 4;
        const float4 v = *(const float4*)(g_p2 + (long long)k * NSMAX + base + s4);
        *(float4*)(sm + B_A + k * B_AS + s4) = v;
    }
    __syncthreads();

    const int ogrp = tid & 7;       // 8 groups x 16 outputs
    const int sgrp = tid >> 3;      // 32 groups x 8 samples
    const int o0 = ogrp * 16;
    const int s0 = sgrp * 8;

    u64 acc[8][8];                  // [s][output-pair]
    {
        const u64* bp = (const u64*)(sm + B_B1) + (o0 >> 1);
        u64 b[8];
#pragma unroll
        for (int j = 0; j < 8; j++) b[j] = bp[j];
#pragma unroll
        for (int ss = 0; ss < 8; ss++)
#pragma unroll
            for (int j = 0; j < 8; j++) acc[ss][j] = b[j];
    }
    {
        const float* ap = sm + B_A + s0;
        const float* wp = sm + B_W1 + o0;
#pragma unroll 2
        for (int k = 0; k < 54; k++) {
            const float4 a0 = *(const float4*)ap;
            const float4 a1 = *(const float4*)(ap + 4);
            const ulonglong2 wA = *(const ulonglong2*)wp;
            const ulonglong2 wB = *(const ulonglong2*)(wp + 4);
            const ulonglong2 wC = *(const ulonglong2*)(wp + 8);
            const ulonglong2 wD = *(const ulonglong2*)(wp + 12);
            u64 ad[8];
            ad[0] = dup2(a0.x); ad[1] = dup2(a0.y); ad[2] = dup2(a0.z); ad[3] = dup2(a0.w);
            ad[4] = dup2(a1.x); ad[5] = dup2(a1.y); ad[6] = dup2(a1.z); ad[7] = dup2(a1.w);
            u64 wv[8] = {wA.x, wA.y, wB.x, wB.y, wC.x, wC.y, wD.x, wD.y};
#pragma unroll
            for (int ss = 0; ss < 8; ss++)
#pragma unroll
                for (int j = 0; j < 8; j++)
                    fma2(acc[ss][j], ad[ss], wv[j]);
            ap += B_AS; wp += 132;
        }
    }
    // relu + store g_h[s][o] (coalesced 16B stores)
#pragma unroll
    for (int ss = 0; ss < 8; ss++) {
        const long long gs = base + s0 + ss;
        if (gs < nsamp) {
            u64* gh = (u64*)(g_h + gs * 128 + o0);
#pragma unroll
            for (int j = 0; j < 4; j++) {
                float2 x0 = unpack2(acc[ss][2 * j]);
                float2 x1 = unpack2(acc[ss][2 * j + 1]);
                ulonglong2 v;
                v.x = pack2(fmaxf(x0.x, 0.0f), fmaxf(x0.y, 0.0f));
                v.y = pack2(fmaxf(x1.x, 0.0f), fmaxf(x1.y, 0.0f));
                *(ulonglong2*)(gh + 2 * j) = v;
            }
        }
    }
}

// ================================================================
// Kernel C: out (128->128) -> d_out
// 256 thr / 256 samples; tile 8 samp x 16 out; 6 LDS.128 / 64 fma2
// ================================================================
#define CTPB2 256
#define C_W2   0                          // [128][132] w2t[k*132+o]
#define C_B2   16896                      // 128
#define C_H    17024                      // [128][260]  h[k*260+s]
#define C_HS   260
#define C_SM_FLOATS (17024 + 128 * 260)   // 50304 -> 201.2KB
#define C_SM_BYTES (C_SM_FLOATS * 4)

__global__ void __launch_bounds__(CTPB2)
out_kernel(const float* __restrict__ w2, const float* __restrict__ b2,
           float* __restrict__ out, int nsamp)
{
    extern __shared__ float sm[];
    const int tid = threadIdx.x;
    const long long base = (long long)blockIdx.x * 256;

    for (int i = tid; i < 16384; i += CTPB2) {
        const int o = i >> 7, k = i & 127;          // coalesced w2 read
        sm[C_W2 + k * 132 + o] = w2[i];
    }
    for (int i = tid; i < 128; i += CTPB2) sm[C_B2 + i] = b2[i];
    // transpose-stage H from g_h[s][o] -> sm[k=o][s]
    for (int i = tid; i < 256 * 32; i += CTPB2) {
        const int ss = i >> 5, o4 = (i & 31) * 4;
        const float4 v = *(const float4*)(g_h + (base + ss) * 128 + o4);
        sm[C_H + (o4 + 0) * C_HS + ss] = v.x;
        sm[C_H + (o4 + 1) * C_HS + ss] = v.y;
        sm[C_H + (o4 + 2) * C_HS + ss] = v.z;
        sm[C_H + (o4 + 3) * C_HS + ss] = v.w;
    }
    __syncthreads();

    const int ogrp = tid & 7;
    const int sgrp = tid >> 3;
    const int o0 = ogrp * 16;
    const int s0 = sgrp * 8;

    u64 acc[8][8];
    {
        const u64* bp = (const u64*)(sm + C_B2) + (o0 >> 1);
        u64 b[8];
#pragma unroll
        for (int j = 0; j < 8; j++) b[j] = bp[j];
#pragma unroll
        for (int ss = 0; ss < 8; ss++)
#pragma unroll
            for (int j = 0; j < 8; j++) acc[ss][j] = b[j];
    }
    {
        const float* hp = sm + C_H + s0;
        const float* wp = sm + C_W2 + o0;
#pragma unroll 2
        for (int k = 0; k < 128; k++) {
            const float4 h0 = *(const float4*)hp;
            const float4 h1 = *(const float4*)(hp + 4);
            const ulonglong2 wA = *(const ulonglong2*)wp;
            const ulonglong2 wB = *(const ulonglong2*)(wp + 4);
            const ulonglong2 wC = *(const ulonglong2*)(wp + 8);
            const ulonglong2 wD = *(const ulonglong2*)(wp + 12);
            u64 hd[8];
            hd[0] = dup2(h0.x); hd[1] = dup2(h0.y); hd[2] = dup2(h0.z); hd[3] = dup2(h0.w);
            hd[4] = dup2(h1.x); hd[5] = dup2(h1.y); hd[6] = dup2(h1.z); hd[7] = dup2(h1.w);
            u64 wv[8] = {wA.x, wA.y, wB.x, wB.y, wC.x, wC.y, wD.x, wD.y};
#pragma unroll
            for (int ss = 0; ss < 8; ss++)
#pragma unroll
                for (int j = 0; j < 8; j++)
                    fma2(acc[ss][j], hd[ss], wv[j]);
            hp += C_HS; wp += 132;
        }
    }
#pragma unroll
    for (int ss = 0; ss < 8; ss++) {
        const long long gs = base + s0 + ss;
        if (gs < nsamp) {
            u64* op = (u64*)(out + gs * 128 + o0);
#pragma unroll
            for (int j = 0; j < 4; j++) {
                ulonglong2 v; v.x = acc[ss][2 * j]; v.y = acc[ss][2 * j + 1];
                *(ulonglong2*)(op + 2 * j) = v;
            }
        }
    }
}

extern "C" void kernel_launch(void* const* d_in, const int* in_sizes, int n_in,
                              void* d_out, int out_size)
{
    const float* x   = (const float*)d_in[0];
    const float* c1w = (const float*)d_in[1];
    const float* c1b = (const float*)d_in[2];
    const float* c2w = (const float*)d_in[3];
    const float* c2b = (const float*)d_in[4];
    const float* w1  = (const float*)d_in[5];
    const float* b1  = (const float*)d_in[6];
    const float* w2  = (const float*)d_in[7];
    const float* b2  = (const float*)d_in[8];
    float* out = (float*)d_out;

    const int nsamp = in_sizes[0] / 128;

    cudaFuncSetAttribute(fc1_kernel, cudaFuncAttributeMaxDynamicSharedMemorySize, B_SM_BYTES);
    cudaFuncSetAttribute(out_kernel, cudaFuncAttributeMaxDynamicSharedMemorySize, C_SM_BYTES);

    conv1_kernel<<<(nsamp + A1TPB - 1) / A1TPB, A1TPB>>>(x, c1w, c1b, nsamp);
    conv2_kernel<<<(nsamp + A2TPB - 1) / A2TPB, A2TPB>>>(c2w, c2b, nsamp);

    const int gblocks = (nsamp + 255) / 256;
    fc1_kernel<<<gblocks, BTPB, B_SM_BYTES>>>(w1, b1, nsamp);
    out_kernel<<<gblocks, CTPB2, C_SM_BYTES>>>(w2, b2, out, nsamp);
}

// round 7
// speedup vs baseline: 1.7960x; 1.2682x over previous
#include <cuda_runtime.h>

typedef unsigned long long u64;

#define NSMAX 131072
__device__ float g_c1[108 * NSMAX];   // conv1+pool output [ch*36+y*6+x][sample]
__device__ float g_p2[54 * NSMAX];    // conv2+pool output [k][sample]
__device__ float g_h [128 * NSMAX];   // fc1 output [o][sample]

__device__ __forceinline__ u64 dup2(float a) {
    u64 r; asm("mov.b64 %0, {%1, %1};" : "=l"(r) : "r"(__float_as_uint(a))); return r;
}
__device__ __forceinline__ u64 pack2(float lo, float hi) {
    u64 r; asm("mov.b64 %0, {%1, %2};" : "=l"(r) : "r"(__float_as_uint(lo)), "r"(__float_as_uint(hi))); return r;
}
__device__ __forceinline__ void fma2(u64& acc, u64 a, u64 b) {
    asm("fma.rn.f32x2 %0, %1, %2, %0;" : "+l"(acc) : "l"(a), "l"(b));
}
__device__ __forceinline__ float2 unpack2(u64 v) {
    unsigned lo, hi; asm("mov.b64 {%0, %1}, %2;" : "=r"(lo), "=r"(hi) : "l"(v));
    return make_float2(__uint_as_float(lo), __uint_as_float(hi));
}

// ================================================================
// Kernel A1: conv1 (1->3, 3x3 pad1, 12x12) + maxpool2 + relu -> g_c1
// ================================================================
#define A1TPB 256
__global__ void __launch_bounds__(A1TPB)
conv1_kernel(const float* __restrict__ x,
             const float* __restrict__ c1w, const float* __restrict__ c1b, int nsamp)
{
    __shared__ float ws[32];
    const int tid = threadIdx.x;
    if (tid < 27) ws[tid] = c1w[tid];
    if (tid < 3)  ws[27 + tid] = c1b[tid];
    __syncthreads();

    const long long s = (long long)blockIdx.x * A1TPB + tid;
    if (s >= nsamp) return;
    const float* xp = x + s * 128;

    float W[27];
#pragma unroll
    for (int i = 0; i < 27; i++) W[i] = ws[i];
    const float B0 = ws[27], B1 = ws[28], B2 = ws[29];

#pragma unroll
    for (int py = 0; py < 6; py++) {
        float r[4][12];
#pragma unroll
        for (int j = 0; j < 4; j++) {
            const int rr = 2 * py - 1 + j;
            if (rr < 0 || rr >= 11) {
#pragma unroll
                for (int c = 0; c < 12; c++) r[j][c] = 0.0f;
            } else if (rr == 10) {
#pragma unroll
                for (int c = 0; c < 8; c += 2) {
                    float2 v = *(const float2*)(xp + 120 + c);
                    r[j][c] = v.x; r[j][c + 1] = v.y;
                }
                r[j][8] = 0.0f; r[j][9] = 0.0f; r[j][10] = 0.0f; r[j][11] = 0.0f;
            } else {
#pragma unroll
                for (int c = 0; c < 12; c += 2) {
                    float2 v = *(const float2*)(xp + 12 * rr + c);
                    r[j][c] = v.x; r[j][c + 1] = v.y;
                }
            }
        }
#pragma unroll
        for (int oc = 0; oc < 3; oc++) {
            float v0[12], v1[12];
#pragma unroll
            for (int cx = 0; cx < 12; cx++) {
                float a0 = 0.0f, a1 = 0.0f;
#pragma unroll
                for (int ky = 0; ky < 3; ky++) {
#pragma unroll
                    for (int kx = 0; kx < 3; kx++) {
                        const int col = cx + kx - 1;
                        if (col >= 0 && col < 12) {
                            const float w = W[oc * 9 + ky * 3 + kx];
                            a0 = fmaf(w, r[ky][col],     a0);
                            a1 = fmaf(w, r[ky + 1][col], a1);
                        }
                    }
                }
                v0[cx] = a0; v1[cx] = a1;
            }
            const float bb = (oc == 0) ? B0 : ((oc == 1) ? B1 : B2);
#pragma unroll
            for (int px = 0; px < 6; px++) {
                float m = fmaxf(fmaxf(v0[2 * px], v0[2 * px + 1]),
                                fmaxf(v1[2 * px], v1[2 * px + 1]));
                g_c1[(long long)(oc * 36 + py * 6 + px) * NSMAX + s] = fmaxf(m + bb, 0.0f);
            }
        }
    }
}

// ================================================================
// Kernel A2: conv2 (3->6, 3x3 pad1, 6x6) + maxpool2 + relu -> g_p2
// ================================================================
#define A2TPB 256
__global__ void __launch_bounds__(A2TPB)
conv2_kernel(const float* __restrict__ c2w, const float* __restrict__ c2b, int nsamp)
{
    __shared__ float ws[168];
    const int tid = threadIdx.x;
    if (tid < 162) ws[tid] = c2w[tid];
    if (tid < 6)   ws[162 + tid] = c2b[tid];
    __syncthreads();

    const long long s = (long long)blockIdx.x * A2TPB + tid;
    if (s >= nsamp) return;

#pragma unroll
    for (int py = 0; py < 3; py++) {
#pragma unroll
        for (int oh = 0; oh < 2; oh++) {
            u64 acc[3][3][2];
#pragma unroll
            for (int q = 0; q < 3; q++)
#pragma unroll
                for (int px = 0; px < 3; px++) { acc[q][px][0] = 0ull; acc[q][px][1] = 0ull; }

#pragma unroll
            for (int ic = 0; ic < 3; ic++) {
                float rw[4][6];
#pragma unroll
                for (int j = 0; j < 4; j++) {
                    const int y = 2 * py - 1 + j;
                    if (y < 0 || y > 5) {
#pragma unroll
                        for (int ix = 0; ix < 6; ix++) rw[j][ix] = 0.0f;
                    } else {
#pragma unroll
                        for (int ix = 0; ix < 6; ix++)
                            rw[j][ix] = g_c1[(long long)(ic * 36 + y * 6 + ix) * NSMAX + s];
                    }
                }
                u64 pc[3][6];
#pragma unroll
                for (int j = 0; j < 3; j++)
#pragma unroll
                    for (int ix = 0; ix < 6; ix++)
                        pc[j][ix] = pack2(rw[j][ix], rw[j + 1][ix]);

#pragma unroll
                for (int q = 0; q < 3; q++) {
                    const int oc = oh * 3 + q;
#pragma unroll
                    for (int ky = 0; ky < 3; ky++) {
#pragma unroll
                        for (int kx = 0; kx < 3; kx++) {
                            const u64 wd = dup2(ws[oc * 27 + ic * 9 + ky * 3 + kx]);
#pragma unroll
                            for (int px = 0; px < 3; px++) {
                                const int ix0 = 2 * px + kx - 1;
                                const int ix1 = 2 * px + kx;
                                if (ix0 >= 0 && ix0 < 6) fma2(acc[q][px][0], wd, pc[ky][ix0]);
                                if (ix1 < 6)             fma2(acc[q][px][1], wd, pc[ky][ix1]);
                            }
                        }
                    }
                }
            }
#pragma unroll
            for (int q = 0; q < 3; q++) {
                const int oc = oh * 3 + q;
                const float bb = ws[162 + oc];
#pragma unroll
                for (int px = 0; px < 3; px++) {
                    float2 v0 = unpack2(acc[q][px][0]), v1 = unpack2(acc[q][px][1]);
                    float m = fmaxf(fmaxf(v0.x, v0.y), fmaxf(v1.x, v1.y));
                    g_p2[(long long)(oc * 9 + py * 3 + px) * NSMAX + s] = fmaxf(m + bb, 0.0f);
                }
            }
        }
    }
}

// ================================================================
// Kernel B: fc1 (54->128) + relu -> g_h[o][s]
// 256 thr / 256 samples; tile 8 samp x 16 out (4 scattered quads)
// ================================================================
#define BTPB 256
#define B_W1   0                         // [54][132]  w1t[k*132+o]
#define B_B1   7128                      // 128
#define B_A    7256                      // [54][260]
#define B_AS   260
#define B_SM_FLOATS (7256 + 54 * 260)
#define B_SM_BYTES (B_SM_FLOATS * 4)

__global__ void __launch_bounds__(BTPB)
fc1_kernel(const float* __restrict__ w1, const float* __restrict__ b1, int nsamp)
{
    extern __shared__ float sm[];
    const int tid = threadIdx.x;
    const long long base = (long long)blockIdx.x * 256;

    for (int i = tid; i < 6912; i += BTPB) {
        const int o = i / 54, k = i - o * 54;
        sm[B_W1 + k * 132 + o] = w1[i];
    }
    for (int i = tid; i < 128; i += BTPB) sm[B_B1 + i] = b1[i];
    for (int i = tid; i < 54 * 64; i += BTPB) {
        const int k = i >> 6, s4 = (i & 63) * 4;
        const float4 v = *(const float4*)(g_p2 + (long long)k * NSMAX + base + s4);
        *(float4*)(sm + B_A + k * B_AS + s4) = v;
    }
    __syncthreads();

    const int ogrp = tid & 7;       // outputs: quads at og4 + 32j
    const int sgrp = tid >> 3;      // 32 groups x 8 samples
    const int og4 = ogrp * 4;
    const int s0 = sgrp * 8;

    u64 acc[8][8];                  // [s][pair j2: quad j=(j2>>1), pair-in-quad j2&1]
    {
        u64 b[8];
#pragma unroll
        for (int j = 0; j < 4; j++) {
            const u64* bp = (const u64*)(sm + B_B1 + og4 + 32 * j);
            b[2 * j] = bp[0]; b[2 * j + 1] = bp[1];
        }
#pragma unroll
        for (int ss = 0; ss < 8; ss++)
#pragma unroll
            for (int j = 0; j < 8; j++) acc[ss][j] = b[j];
    }
    {
        const float* ap = sm + B_A + s0;
        const float* wp = sm + B_W1 + og4;
#pragma unroll 2
        for (int k = 0; k < 54; k++) {
            const float4 a0 = *(const float4*)ap;
            const float4 a1 = *(const float4*)(ap + 4);
            const ulonglong2 wA = *(const ulonglong2*)wp;           // o: og4+0..3
            const ulonglong2 wB = *(const ulonglong2*)(wp + 32);    // o: og4+32..35
            const ulonglong2 wC = *(const ulonglong2*)(wp + 64);
            const ulonglong2 wD = *(const ulonglong2*)(wp + 96);
            u64 ad[8];
            ad[0] = dup2(a0.x); ad[1] = dup2(a0.y); ad[2] = dup2(a0.z); ad[3] = dup2(a0.w);
            ad[4] = dup2(a1.x); ad[5] = dup2(a1.y); ad[6] = dup2(a1.z); ad[7] = dup2(a1.w);
            u64 wv[8] = {wA.x, wA.y, wB.x, wB.y, wC.x, wC.y, wD.x, wD.y};
#pragma unroll
            for (int ss = 0; ss < 8; ss++)
#pragma unroll
                for (int j = 0; j < 8; j++)
                    fma2(acc[ss][j], ad[ss], wv[j]);
            ap += B_AS; wp += 132;
        }
    }
    // relu + store g_h[o][s]: per output o, 8 sample values -> 2 float4
#pragma unroll
    for (int j2 = 0; j2 < 8; j2++) {
        const int o_even = og4 + 32 * (j2 >> 1) + 2 * (j2 & 1);
        float lo[8], hi[8];
#pragma unroll
        for (int ss = 0; ss < 8; ss++) {
            float2 v = unpack2(acc[ss][j2]);
            lo[ss] = fmaxf(v.x, 0.0f);
            hi[ss] = fmaxf(v.y, 0.0f);
        }
        float* ge = g_h + (long long)o_even * NSMAX + base + s0;
        float* go = g_h + (long long)(o_even + 1) * NSMAX + base + s0;
        *(float4*)ge       = make_float4(lo[0], lo[1], lo[2], lo[3]);
        *(float4*)(ge + 4) = make_float4(lo[4], lo[5], lo[6], lo[7]);
        *(float4*)go       = make_float4(hi[0], hi[1], hi[2], hi[3]);
        *(float4*)(go + 4) = make_float4(hi[4], hi[5], hi[6], hi[7]);
    }
}

// ================================================================
// Kernel C: out (128->128) -> d_out
// 256 thr / 256 samples; tile 8 samp x 16 out (4 scattered quads)
// ================================================================
#define CTPB2 256
#define C_W2   0                          // [128][132]
#define C_B2   16896                      // 128
#define C_H    17024                      // [128][260]
#define C_HS   260
#define C_SM_FLOATS (17024 + 128 * 260)
#define C_SM_BYTES (C_SM_FLOATS * 4)

__global__ void __launch_bounds__(CTPB2)
out_kernel(const float* __restrict__ w2, const float* __restrict__ b2,
           float* __restrict__ out, int nsamp)
{
    extern __shared__ float sm[];
    const int tid = threadIdx.x;
    const long long base = (long long)blockIdx.x * 256;

    for (int i = tid; i < 16384; i += CTPB2) {
        const int o = i >> 7, k = i & 127;
        sm[C_W2 + k * 132 + o] = w2[i];
    }
    for (int i = tid; i < 128; i += CTPB2) sm[C_B2 + i] = b2[i];
    for (int i = tid; i < 128 * 64; i += CTPB2) {
        const int k = i >> 6, s4 = (i & 63) * 4;
        const float4 v = *(const float4*)(g_h + (long long)k * NSMAX + base + s4);
        *(float4*)(sm + C_H + k * C_HS + s4) = v;
    }
    __syncthreads();

    const int ogrp = tid & 7;
    const int sgrp = tid >> 3;
    const int og4 = ogrp * 4;
    const int s0 = sgrp * 8;

    u64 acc[8][8];
    {
        u64 b[8];
#pragma unroll
        for (int j = 0; j < 4; j++) {
            const u64* bp = (const u64*)(sm + C_B2 + og4 + 32 * j);
            b[2 * j] = bp[0]; b[2 * j + 1] = bp[1];
        }
#pragma unroll
        for (int ss = 0; ss < 8; ss++)
#pragma unroll
            for (int j = 0; j < 8; j++) acc[ss][j] = b[j];
    }
    {
        const float* hp = sm + C_H + s0;
        const float* wp = sm + C_W2 + og4;
#pragma unroll 2
        for (int k = 0; k < 128; k++) {
            const float4 h0 = *(const float4*)hp;
            const float4 h1 = *(const float4*)(hp + 4);
            const ulonglong2 wA = *(const ulonglong2*)wp;
            const ulonglong2 wB = *(const ulonglong2*)(wp + 32);
            const ulonglong2 wC = *(const ulonglong2*)(wp + 64);
            const ulonglong2 wD = *(const ulonglong2*)(wp + 96);
            u64 hd[8];
            hd[0] = dup2(h0.x); hd[1] = dup2(h0.y); hd[2] = dup2(h0.z); hd[3] = dup2(h0.w);
            hd[4] = dup2(h1.x); hd[5] = dup2(h1.y); hd[6] = dup2(h1.z); hd[7] = dup2(h1.w);
            u64 wv[8] = {wA.x, wA.y, wB.x, wB.y, wC.x, wC.y, wD.x, wD.y};
#pragma unroll
            for (int ss = 0; ss < 8; ss++)
#pragma unroll
                for (int j = 0; j < 8; j++)
                    fma2(acc[ss][j], hd[ss], wv[j]);
            hp += C_HS; wp += 132;
        }
    }
    // store: per sample, 4 quads at o = og4 + 32j (16B each, coalesced across ogrp)
#pragma unroll
    for (int ss = 0; ss < 8; ss++) {
        const long long gs = base + s0 + ss;
        if (gs < nsamp) {
            float* op = out + gs * 128;
#pragma unroll
            for (int j = 0; j < 4; j++) {
                ulonglong2 v; v.x = acc[ss][2 * j]; v.y = acc[ss][2 * j + 1];
                *(ulonglong2*)(op + og4 + 32 * j) = v;
            }
        }
    }
}

extern "C" void kernel_launch(void* const* d_in, const int* in_sizes, int n_in,
                              void* d_out, int out_size)
{
    const float* x   = (const float*)d_in[0];
    const float* c1w = (const float*)d_in[1];
    const float* c1b = (const float*)d_in[2];
    const float* c2w = (const float*)d_in[3];
    const float* c2b = (const float*)d_in[4];
    const float* w1  = (const float*)d_in[5];
    const float* b1  = (const float*)d_in[6];
    const float* w2  = (const float*)d_in[7];
    const float* b2  = (const float*)d_in[8];
    float* out = (float*)d_out;

    const int nsamp = in_sizes[0] / 128;

    cudaFuncSetAttribute(fc1_kernel, cudaFuncAttributeMaxDynamicSharedMemorySize, B_SM_BYTES);
    cudaFuncSetAttribute(out_kernel, cudaFuncAttributeMaxDynamicSharedMemorySize, C_SM_BYTES);

    conv1_kernel<<<(nsamp + A1TPB - 1) / A1TPB, A1TPB>>>(x, c1w, c1b, nsamp);
    conv2_kernel<<<(nsamp + A2TPB - 1) / A2TPB, A2TPB>>>(c2w, c2b, nsamp);

    const int gblocks = (nsamp + 255) / 256;
    fc1_kernel<<<gblocks, BTPB, B_SM_BYTES>>>(w1, b1, nsamp);
    out_kernel<<<gblocks, CTPB2, C_SM_BYTES>>>(w2, b2, out, nsamp);
}

// round 8
// speedup vs baseline: 1.9072x; 1.0619x over previous
#include <cuda_runtime.h>

typedef unsigned long long u64;

#define NSMAX 131072
__device__ float g_c1[108 * NSMAX];   // conv1+pool output [ch*36+y*6+x][sample]
__device__ float g_p2[54 * NSMAX];    // conv2+pool output [k][sample]
__device__ float g_h [128 * NSMAX];   // fc1 output [o][sample]

__device__ __forceinline__ u64 dup2(float a) {
    u64 r; asm("mov.b64 %0, {%1, %1};" : "=l"(r) : "r"(__float_as_uint(a))); return r;
}
__device__ __forceinline__ u64 pack2(float lo, float hi) {
    u64 r; asm("mov.b64 %0, {%1, %2};" : "=l"(r) : "r"(__float_as_uint(lo)), "r"(__float_as_uint(hi))); return r;
}
__device__ __forceinline__ void fma2(u64& acc, u64 a, u64 b) {
    asm("fma.rn.f32x2 %0, %1, %2, %0;" : "+l"(acc) : "l"(a), "l"(b));
}
__device__ __forceinline__ float2 unpack2(u64 v) {
    unsigned lo, hi; asm("mov.b64 {%0, %1}, %2;" : "=r"(lo), "=r"(hi) : "l"(v));
    return make_float2(__uint_as_float(lo), __uint_as_float(hi));
}

// ================================================================
// Kernel A1: conv1 (1->3, 3x3 pad1, 12x12) + maxpool2 + relu -> g_c1
// ================================================================
#define A1TPB 256
__global__ void __launch_bounds__(A1TPB)
conv1_kernel(const float* __restrict__ x,
             const float* __restrict__ c1w, const float* __restrict__ c1b, int nsamp)
{
    __shared__ float ws[32];
    const int tid = threadIdx.x;
    if (tid < 27) ws[tid] = c1w[tid];
    if (tid < 3)  ws[27 + tid] = c1b[tid];
    __syncthreads();

    const long long s = (long long)blockIdx.x * A1TPB + tid;
    if (s >= nsamp) return;
    const float* xp = x + s * 128;

    float W[27];
#pragma unroll
    for (int i = 0; i < 27; i++) W[i] = ws[i];
    const float B0 = ws[27], B1 = ws[28], B2 = ws[29];

#pragma unroll
    for (int py = 0; py < 6; py++) {
        float r[4][12];
#pragma unroll
        for (int j = 0; j < 4; j++) {
            const int rr = 2 * py - 1 + j;
            if (rr < 0 || rr >= 11) {
#pragma unroll
                for (int c = 0; c < 12; c++) r[j][c] = 0.0f;
            } else if (rr == 10) {
#pragma unroll
                for (int c = 0; c < 8; c += 2) {
                    float2 v = *(const float2*)(xp + 120 + c);
                    r[j][c] = v.x; r[j][c + 1] = v.y;
                }
                r[j][8] = 0.0f; r[j][9] = 0.0f; r[j][10] = 0.0f; r[j][11] = 0.0f;
            } else {
#pragma unroll
                for (int c = 0; c < 12; c += 2) {
                    float2 v = *(const float2*)(xp + 12 * rr + c);
                    r[j][c] = v.x; r[j][c + 1] = v.y;
                }
            }
        }
#pragma unroll
        for (int oc = 0; oc < 3; oc++) {
            float v0[12], v1[12];
#pragma unroll
            for (int cx = 0; cx < 12; cx++) {
                float a0 = 0.0f, a1 = 0.0f;
#pragma unroll
                for (int ky = 0; ky < 3; ky++) {
#pragma unroll
                    for (int kx = 0; kx < 3; kx++) {
                        const int col = cx + kx - 1;
                        if (col >= 0 && col < 12) {
                            const float w = W[oc * 9 + ky * 3 + kx];
                            a0 = fmaf(w, r[ky][col],     a0);
                            a1 = fmaf(w, r[ky + 1][col], a1);
                        }
                    }
                }
                v0[cx] = a0; v1[cx] = a1;
            }
            const float bb = (oc == 0) ? B0 : ((oc == 1) ? B1 : B2);
#pragma unroll
            for (int px = 0; px < 6; px++) {
                float m = fmaxf(fmaxf(v0[2 * px], v0[2 * px + 1]),
                                fmaxf(v1[2 * px], v1[2 * px + 1]));
                g_c1[(long long)(oc * 36 + py * 6 + px) * NSMAX + s] = fmaxf(m + bb, 0.0f);
            }
        }
    }
}

// ================================================================
// Kernel A2: conv2 (3->6, 3x3 pad1, 6x6) + maxpool2 + relu -> g_p2
// ================================================================
#define A2TPB 256
__global__ void __launch_bounds__(A2TPB)
conv2_kernel(const float* __restrict__ c2w, const float* __restrict__ c2b, int nsamp)
{
    __shared__ float ws[168];
    const int tid = threadIdx.x;
    if (tid < 162) ws[tid] = c2w[tid];
    if (tid < 6)   ws[162 + tid] = c2b[tid];
    __syncthreads();

    const long long s = (long long)blockIdx.x * A2TPB + tid;
    if (s >= nsamp) return;

#pragma unroll
    for (int py = 0; py < 3; py++) {
#pragma unroll
        for (int oh = 0; oh < 2; oh++) {
            u64 acc[3][3][2];
#pragma unroll
            for (int q = 0; q < 3; q++)
#pragma unroll
                for (int px = 0; px < 3; px++) { acc[q][px][0] = 0ull; acc[q][px][1] = 0ull; }

#pragma unroll
            for (int ic = 0; ic < 3; ic++) {
                float rw[4][6];
#pragma unroll
                for (int j = 0; j < 4; j++) {
                    const int y = 2 * py - 1 + j;
                    if (y < 0 || y > 5) {
#pragma unroll
                        for (int ix = 0; ix < 6; ix++) rw[j][ix] = 0.0f;
                    } else {
#pragma unroll
                        for (int ix = 0; ix < 6; ix++)
                            rw[j][ix] = g_c1[(long long)(ic * 36 + y * 6 + ix) * NSMAX + s];
                    }
                }
                u64 pc[3][6];
#pragma unroll
                for (int j = 0; j < 3; j++)
#pragma unroll
                    for (int ix = 0; ix < 6; ix++)
                        pc[j][ix] = pack2(rw[j][ix], rw[j + 1][ix]);

#pragma unroll
                for (int q = 0; q < 3; q++) {
                    const int oc = oh * 3 + q;
#pragma unroll
                    for (int ky = 0; ky < 3; ky++) {
#pragma unroll
                        for (int kx = 0; kx < 3; kx++) {
                            const u64 wd = dup2(ws[oc * 27 + ic * 9 + ky * 3 + kx]);
#pragma unroll
                            for (int px = 0; px < 3; px++) {
                                const int ix0 = 2 * px + kx - 1;
                                const int ix1 = 2 * px + kx;
                                if (ix0 >= 0 && ix0 < 6) fma2(acc[q][px][0], wd, pc[ky][ix0]);
                                if (ix1 < 6)             fma2(acc[q][px][1], wd, pc[ky][ix1]);
                            }
                        }
                    }
                }
            }
#pragma unroll
            for (int q = 0; q < 3; q++) {
                const int oc = oh * 3 + q;
                const float bb = ws[162 + oc];
#pragma unroll
                for (int px = 0; px < 3; px++) {
                    float2 v0 = unpack2(acc[q][px][0]), v1 = unpack2(acc[q][px][1]);
                    float m = fmaxf(fmaxf(v0.x, v0.y), fmaxf(v1.x, v1.y));
                    g_p2[(long long)(oc * 9 + py * 3 + px) * NSMAX + s] = fmaxf(m + bb, 0.0f);
                }
            }
        }
    }
}

// ================================================================
// Kernel B: fc1 (54->128) + relu -> g_h[o][s]
// 512 thr / 256 samples; tile 8 samp x 8 out (quads at og4, og4+64)
// ================================================================
#define BTPB 512
#define B_W1   0                         // [54][132]  w1t[k*132+o]
#define B_B1   7128                      // 128
#define B_A    7256                      // [54][260]
#define B_AS   260
#define B_SM_FLOATS (7256 + 54 * 260)
#define B_SM_BYTES (B_SM_FLOATS * 4)

__global__ void __launch_bounds__(BTPB)
fc1_kernel(const float* __restrict__ w1, const float* __restrict__ b1, int nsamp)
{
    extern __shared__ float sm[];
    const int tid = threadIdx.x;
    const long long base = (long long)blockIdx.x * 256;

    for (int i = tid; i < 6912; i += BTPB) {
        const int o = i / 54, k = i - o * 54;
        sm[B_W1 + k * 132 + o] = w1[i];
    }
    for (int i = tid; i < 128; i += BTPB) sm[B_B1 + i] = b1[i];
    for (int i = tid; i < 54 * 64; i += BTPB) {
        const int k = i >> 6, s4 = (i & 63) * 4;
        const float4 v = *(const float4*)(g_p2 + (long long)k * NSMAX + base + s4);
        *(float4*)(sm + B_A + k * B_AS + s4) = v;
    }
    __syncthreads();

    const int ogrp = tid & 15;      // 16 groups: quads at og4, og4+64
    const int sgrp = tid >> 4;      // 32 groups x 8 samples
    const int og4 = ogrp * 4;
    const int s0 = sgrp * 8;

    u64 acc[8][4];                  // [s][pair: q0p0,q0p1,q1p0,q1p1]
    {
        const u64* bpA = (const u64*)(sm + B_B1 + og4);
        const u64* bpB = (const u64*)(sm + B_B1 + og4 + 64);
        const u64 b0 = bpA[0], b1v = bpA[1], b2 = bpB[0], b3 = bpB[1];
#pragma unroll
        for (int ss = 0; ss < 8; ss++) {
            acc[ss][0] = b0; acc[ss][1] = b1v; acc[ss][2] = b2; acc[ss][3] = b3;
        }
    }
    {
        const float* ap = sm + B_A + s0;
        const float* wp = sm + B_W1 + og4;
#pragma unroll 3
        for (int k = 0; k < 54; k++) {
            const float4 a0 = *(const float4*)ap;
            const float4 a1 = *(const float4*)(ap + 4);
            const ulonglong2 wA = *(const ulonglong2*)wp;           // o: og4..og4+3
            const ulonglong2 wB = *(const ulonglong2*)(wp + 64);    // o: og4+64..+67
            u64 ad[8];
            ad[0] = dup2(a0.x); ad[1] = dup2(a0.y); ad[2] = dup2(a0.z); ad[3] = dup2(a0.w);
            ad[4] = dup2(a1.x); ad[5] = dup2(a1.y); ad[6] = dup2(a1.z); ad[7] = dup2(a1.w);
#pragma unroll
            for (int ss = 0; ss < 8; ss++) {
                fma2(acc[ss][0], ad[ss], wA.x);
                fma2(acc[ss][1], ad[ss], wA.y);
                fma2(acc[ss][2], ad[ss], wB.x);
                fma2(acc[ss][3], ad[ss], wB.y);
            }
            ap += B_AS; wp += 132;
        }
    }
    // relu + store g_h[o][s]: 8 outputs, 8 samples each -> 2 float4 per output
#pragma unroll
    for (int j = 0; j < 4; j++) {
        const int o_even = og4 + 2 * (j & 1) + 64 * (j >> 1);
        float lo[8], hi[8];
#pragma unroll
        for (int ss = 0; ss < 8; ss++) {
            float2 v = unpack2(acc[ss][j]);
            lo[ss] = fmaxf(v.x, 0.0f);
            hi[ss] = fmaxf(v.y, 0.0f);
        }
        float* ge = g_h + (long long)o_even * NSMAX + base + s0;
        float* go = g_h + (long long)(o_even + 1) * NSMAX + base + s0;
        *(float4*)ge       = make_float4(lo[0], lo[1], lo[2], lo[3]);
        *(float4*)(ge + 4) = make_float4(lo[4], lo[5], lo[6], lo[7]);
        *(float4*)go       = make_float4(hi[0], hi[1], hi[2], hi[3]);
        *(float4*)(go + 4) = make_float4(hi[4], hi[5], hi[6], hi[7]);
    }
}

// ================================================================
// Kernel C: out (128->128) -> d_out
// 512 thr / 256 samples; tile 8 samp x 8 out (quads at og4, og4+64)
// ================================================================
#define CTPB2 512
#define C_W2   0                          // [128][132]
#define C_B2   16896                      // 128
#define C_H    17024                      // [128][260]
#define C_HS   260
#define C_SM_FLOATS (17024 + 128 * 260)
#define C_SM_BYTES (C_SM_FLOATS * 4)

__global__ void __launch_bounds__(CTPB2)
out_kernel(const float* __restrict__ w2, const float* __restrict__ b2,
           float* __restrict__ out, int nsamp)
{
    extern __shared__ float sm[];
    const int tid = threadIdx.x;
    const long long base = (long long)blockIdx.x * 256;

    for (int i = tid; i < 16384; i += CTPB2) {
        const int o = i >> 7, k = i & 127;
        sm[C_W2 + k * 132 + o] = w2[i];
    }
    for (int i = tid; i < 128; i += CTPB2) sm[C_B2 + i] = b2[i];
    for (int i = tid; i < 128 * 64; i += CTPB2) {
        const int k = i >> 6, s4 = (i & 63) * 4;
        const float4 v = *(const float4*)(g_h + (long long)k * NSMAX + base + s4);
        *(float4*)(sm + C_H + k * C_HS + s4) = v;
    }
    __syncthreads();

    const int ogrp = tid & 15;
    const int sgrp = tid >> 4;
    const int og4 = ogrp * 4;
    const int s0 = sgrp * 8;

    u64 acc[8][4];
    {
        const u64* bpA = (const u64*)(sm + C_B2 + og4);
        const u64* bpB = (const u64*)(sm + C_B2 + og4 + 64);
        const u64 b0 = bpA[0], b1v = bpA[1], b2v = bpB[0], b3 = bpB[1];
#pragma unroll
        for (int ss = 0; ss < 8; ss++) {
            acc[ss][0] = b0; acc[ss][1] = b1v; acc[ss][2] = b2v; acc[ss][3] = b3;
        }
    }
    {
        const float* hp = sm + C_H + s0;
        const float* wp = sm + C_W2 + og4;
#pragma unroll 4
        for (int k = 0; k < 128; k++) {
            const float4 h0 = *(const float4*)hp;
            const float4 h1 = *(const float4*)(hp + 4);
            const ulonglong2 wA = *(const ulonglong2*)wp;
            const ulonglong2 wB = *(const ulonglong2*)(wp + 64);
            u64 hd[8];
            hd[0] = dup2(h0.x); hd[1] = dup2(h0.y); hd[2] = dup2(h0.z); hd[3] = dup2(h0.w);
            hd[4] = dup2(h1.x); hd[5] = dup2(h1.y); hd[6] = dup2(h1.z); hd[7] = dup2(h1.w);
#pragma unroll
            for (int ss = 0; ss < 8; ss++) {
                fma2(acc[ss][0], hd[ss], wA.x);
                fma2(acc[ss][1], hd[ss], wA.y);
                fma2(acc[ss][2], hd[ss], wB.x);
                fma2(acc[ss][3], hd[ss], wB.y);
            }
            hp += C_HS; wp += 132;
        }
    }
    // store: per sample, 2 quads at o = og4, og4+64 (16B, coalesced across ogrp)
#pragma unroll
    for (int ss = 0; ss < 8; ss++) {
        const long long gs = base + s0 + ss;
        if (gs < nsamp) {
            float* op = out + gs * 128;
            ulonglong2 v0; v0.x = acc[ss][0]; v0.y = acc[ss][1];
            ulonglong2 v1; v1.x = acc[ss][2]; v1.y = acc[ss][3];
            *(ulonglong2*)(op + og4)      = v0;
            *(ulonglong2*)(op + og4 + 64) = v1;
        }
    }
}

extern "C" void kernel_launch(void* const* d_in, const int* in_sizes, int n_in,
                              void* d_out, int out_size)
{
    const float* x   = (const float*)d_in[0];
    const float* c1w = (const float*)d_in[1];
    const float* c1b = (const float*)d_in[2];
    const float* c2w = (const float*)d_in[3];
    const float* c2b = (const float*)d_in[4];
    const float* w1  = (const float*)d_in[5];
    const float* b1  = (const float*)d_in[6];
    const float* w2  = (const float*)d_in[7];
    const float* b2  = (const float*)d_in[8];
    float* out = (float*)d_out;

    const int nsamp = in_sizes[0] / 128;

    cudaFuncSetAttribute(fc1_kernel, cudaFuncAttributeMaxDynamicSharedMemorySize, B_SM_BYTES);
    cudaFuncSetAttribute(out_kernel, cudaFuncAttributeMaxDynamicSharedMemorySize, C_SM_BYTES);

    conv1_kernel<<<(nsamp + A1TPB - 1) / A1TPB, A1TPB>>>(x, c1w, c1b, nsamp);
    conv2_kernel<<<(nsamp + A2TPB - 1) / A2TPB, A2TPB>>>(c2w, c2b, nsamp);

    const int gblocks = (nsamp + 255) / 256;
    fc1_kernel<<<gblocks, BTPB, B_SM_BYTES>>>(w1, b1, nsamp);
    out_kernel<<<gblocks, CTPB2, C_SM_BYTES>>>(w2, b2, out, nsamp);
}

// round 10
// speedup vs baseline: 2.5160x; 1.3192x over previous
#include <cuda_runtime.h>
#include <cuda_bf16.h>
#include <cstdint>

typedef unsigned long long u64;

#define NSMAX 131072
__device__ float g_c1[108 * NSMAX];   // conv1+pool output [ch*36+y*6+x][sample]
__device__ float g_p2[54 * NSMAX];    // conv2+pool output [k][sample]
__device__ float g_h [NSMAX * 128];   // fc1 output [sample][o] row-major

__device__ __forceinline__ u64 dup2(float a) {
    u64 r; asm("mov.b64 %0, {%1, %1};" : "=l"(r) : "r"(__float_as_uint(a))); return r;
}
__device__ __forceinline__ u64 pack2(float lo, float hi) {
    u64 r; asm("mov.b64 %0, {%1, %2};" : "=l"(r) : "r"(__float_as_uint(lo)), "r"(__float_as_uint(hi))); return r;
}
__device__ __forceinline__ void fma2(u64& acc, u64 a, u64 b) {
    asm("fma.rn.f32x2 %0, %1, %2, %0;" : "+l"(acc) : "l"(a), "l"(b));
}
__device__ __forceinline__ float2 unpack2(u64 v) {
    unsigned lo, hi; asm("mov.b64 {%0, %1}, %2;" : "=r"(lo), "=r"(hi) : "l"(v));
    return make_float2(__uint_as_float(lo), __uint_as_float(hi));
}

// ================================================================
// Kernel A1: conv1 (1->3, 3x3 pad1, 12x12) + maxpool2 + relu -> g_c1
// ================================================================
#define A1TPB 256
__global__ void __launch_bounds__(A1TPB)
conv1_kernel(const float* __restrict__ x,
             const float* __restrict__ c1w, const float* __restrict__ c1b, int nsamp)
{
    __shared__ float ws[32];
    const int tid = threadIdx.x;
    if (tid < 27) ws[tid] = c1w[tid];
    if (tid < 3)  ws[27 + tid] = c1b[tid];
    __syncthreads();

    const long long s = (long long)blockIdx.x * A1TPB + tid;
    if (s >= nsamp) return;
    const float* xp = x + s * 128;

    float W[27];
#pragma unroll
    for (int i = 0; i < 27; i++) W[i] = ws[i];
    const float B0 = ws[27], B1 = ws[28], B2 = ws[29];

#pragma unroll
    for (int py = 0; py < 6; py++) {
        float r[4][12];
#pragma unroll
        for (int j = 0; j < 4; j++) {
            const int rr = 2 * py - 1 + j;
            if (rr < 0 || rr >= 11) {
#pragma unroll
                for (int c = 0; c < 12; c++) r[j][c] = 0.0f;
            } else if (rr == 10) {
#pragma unroll
                for (int c = 0; c < 8; c += 2) {
                    float2 v = *(const float2*)(xp + 120 + c);
                    r[j][c] = v.x; r[j][c + 1] = v.y;
                }
                r[j][8] = 0.0f; r[j][9] = 0.0f; r[j][10] = 0.0f; r[j][11] = 0.0f;
            } else {
#pragma unroll
                for (int c = 0; c < 12; c += 2) {
                    float2 v = *(const float2*)(xp + 12 * rr + c);
                    r[j][c] = v.x; r[j][c + 1] = v.y;
                }
            }
        }
#pragma unroll
        for (int oc = 0; oc < 3; oc++) {
            float v0[12], v1[12];
#pragma unroll
            for (int cx = 0; cx < 12; cx++) {
                float a0 = 0.0f, a1 = 0.0f;
#pragma unroll
                for (int ky = 0; ky < 3; ky++) {
#pragma unroll
                    for (int kx = 0; kx < 3; kx++) {
                        const int col = cx + kx - 1;
                        if (col >= 0 && col < 12) {
                            const float w = W[oc * 9 + ky * 3 + kx];
                            a0 = fmaf(w, r[ky][col],     a0);
                            a1 = fmaf(w, r[ky + 1][col], a1);
                        }
                    }
                }
                v0[cx] = a0; v1[cx] = a1;
            }
            const float bb = (oc == 0) ? B0 : ((oc == 1) ? B1 : B2);
#pragma unroll
            for (int px = 0; px < 6; px++) {
                float m = fmaxf(fmaxf(v0[2 * px], v0[2 * px + 1]),
                                fmaxf(v1[2 * px], v1[2 * px + 1]));
                g_c1[(long long)(oc * 36 + py * 6 + px) * NSMAX + s] = fmaxf(m + bb, 0.0f);
            }
        }
    }
}

// ================================================================
// Kernel A2: conv2 (3->6, 3x3 pad1, 6x6) + maxpool2 + relu -> g_p2
// ================================================================
#define A2TPB 256
__global__ void __launch_bounds__(A2TPB)
conv2_kernel(const float* __restrict__ c2w, const float* __restrict__ c2b, int nsamp)
{
    __shared__ float ws[168];
    const int tid = threadIdx.x;
    if (tid < 162) ws[tid] = c2w[tid];
    if (tid < 6)   ws[162 + tid] = c2b[tid];
    __syncthreads();

    const long long s = (long long)blockIdx.x * A2TPB + tid;
    if (s >= nsamp) return;

#pragma unroll
    for (int py = 0; py < 3; py++) {
#pragma unroll
        for (int oh = 0; oh < 2; oh++) {
            u64 acc[3][3][2];
#pragma unroll
            for (int q = 0; q < 3; q++)
#pragma unroll
                for (int px = 0; px < 3; px++) { acc[q][px][0] = 0ull; acc[q][px][1] = 0ull; }

#pragma unroll
            for (int ic = 0; ic < 3; ic++) {
                float rw[4][6];
#pragma unroll
                for (int j = 0; j < 4; j++) {
                    const int y = 2 * py - 1 + j;
                    if (y < 0 || y > 5) {
#pragma unroll
                        for (int ix = 0; ix < 6; ix++) rw[j][ix] = 0.0f;
                    } else {
#pragma unroll
                        for (int ix = 0; ix < 6; ix++)
                            rw[j][ix] = g_c1[(long long)(ic * 36 + y * 6 + ix) * NSMAX + s];
                    }
                }
                u64 pc[3][6];
#pragma unroll
                for (int j = 0; j < 3; j++)
#pragma unroll
                    for (int ix = 0; ix < 6; ix++)
                        pc[j][ix] = pack2(rw[j][ix], rw[j + 1][ix]);

#pragma unroll
                for (int q = 0; q < 3; q++) {
                    const int oc = oh * 3 + q;
#pragma unroll
                    for (int ky = 0; ky < 3; ky++) {
#pragma unroll
                        for (int kx = 0; kx < 3; kx++) {
                            const u64 wd = dup2(ws[oc * 27 + ic * 9 + ky * 3 + kx]);
#pragma unroll
                            for (int px = 0; px < 3; px++) {
                                const int ix0 = 2 * px + kx - 1;
                                const int ix1 = 2 * px + kx;
                                if (ix0 >= 0 && ix0 < 6) fma2(acc[q][px][0], wd, pc[ky][ix0]);
                                if (ix1 < 6)             fma2(acc[q][px][1], wd, pc[ky][ix1]);
                            }
                        }
                    }
                }
            }
#pragma unroll
            for (int q = 0; q < 3; q++) {
                const int oc = oh * 3 + q;
                const float bb = ws[162 + oc];
#pragma unroll
                for (int px = 0; px < 3; px++) {
                    float2 v0 = unpack2(acc[q][px][0]), v1 = unpack2(acc[q][px][1]);
                    float m = fmaxf(fmaxf(v0.x, v0.y), fmaxf(v1.x, v1.y));
                    g_p2[(long long)(oc * 9 + py * 3 + px) * NSMAX + s] = fmaxf(m + bb, 0.0f);
                }
            }
        }
    }
}

// ================================================================
// Kernel B: fc1 (54->128) + relu -> g_h[s][o] (row-major per sample)
// ================================================================
#define BTPB 512
#define B_W1   0
#define B_B1   7128
#define B_A    7256
#define B_AS   260
#define B_SM_FLOATS (7256 + 54 * 260)
#define B_SM_BYTES (B_SM_FLOATS * 4)

__global__ void __launch_bounds__(BTPB)
fc1_kernel(const float* __restrict__ w1, const float* __restrict__ b1, int nsamp)
{
    extern __shared__ float sm[];
    const int tid = threadIdx.x;
    const long long base = (long long)blockIdx.x * 256;

    for (int i = tid; i < 6912; i += BTPB) {
        const int o = i / 54, k = i - o * 54;
        sm[B_W1 + k * 132 + o] = w1[i];
    }
    for (int i = tid; i < 128; i += BTPB) sm[B_B1 + i] = b1[i];
    for (int i = tid; i < 54 * 64; i += BTPB) {
        const int k = i >> 6, s4 = (i & 63) * 4;
        const float4 v = *(const float4*)(g_p2 + (long long)k * NSMAX + base + s4);
        *(float4*)(sm + B_A + k * B_AS + s4) = v;
    }
    __syncthreads();

    const int ogrp = tid & 15;
    const int sgrp = tid >> 4;
    const int og4 = ogrp * 4;
    const int s0 = sgrp * 8;

    u64 acc[8][4];
    {
        const u64* bpA = (const u64*)(sm + B_B1 + og4);
        const u64* bpB = (const u64*)(sm + B_B1 + og4 + 64);
        const u64 b0 = bpA[0], b1v = bpA[1], b2 = bpB[0], b3 = bpB[1];
#pragma unroll
        for (int ss = 0; ss < 8; ss++) {
            acc[ss][0] = b0; acc[ss][1] = b1v; acc[ss][2] = b2; acc[ss][3] = b3;
        }
    }
    {
        const float* ap = sm + B_A + s0;
        const float* wp = sm + B_W1 + og4;
#pragma unroll 3
        for (int k = 0; k < 54; k++) {
            const float4 a0 = *(const float4*)ap;
            const float4 a1 = *(const float4*)(ap + 4);
            const ulonglong2 wA = *(const ulonglong2*)wp;
            const ulonglong2 wB = *(const ulonglong2*)(wp + 64);
            u64 ad[8];
            ad[0] = dup2(a0.x); ad[1] = dup2(a0.y); ad[2] = dup2(a0.z); ad[3] = dup2(a0.w);
            ad[4] = dup2(a1.x); ad[5] = dup2(a1.y); ad[6] = dup2(a1.z); ad[7] = dup2(a1.w);
#pragma unroll
            for (int ss = 0; ss < 8; ss++) {
                fma2(acc[ss][0], ad[ss], wA.x);
                fma2(acc[ss][1], ad[ss], wA.y);
                fma2(acc[ss][2], ad[ss], wB.x);
                fma2(acc[ss][3], ad[ss], wB.y);
            }
            ap += B_AS; wp += 132;
        }
    }
    // relu + store g_h[s][o]
#pragma unroll
    for (int ss = 0; ss < 8; ss++) {
        const long long gs = base + s0 + ss;
        if (gs < nsamp) {
            float2 p0 = unpack2(acc[ss][0]);
            float2 p1 = unpack2(acc[ss][1]);
            float2 p2v = unpack2(acc[ss][2]);
            float2 p3 = unpack2(acc[ss][3]);
            float4 vA = make_float4(fmaxf(p0.x, 0.f), fmaxf(p0.y, 0.f),
                                    fmaxf(p1.x, 0.f), fmaxf(p1.y, 0.f));
            float4 vB = make_float4(fmaxf(p2v.x, 0.f), fmaxf(p2v.y, 0.f),
                                    fmaxf(p3.x, 0.f), fmaxf(p3.y, 0.f));
            *(float4*)(g_h + gs * 128 + og4)      = vA;
            *(float4*)(g_h + gs * 128 + og4 + 64) = vB;
        }
    }
}

// ================================================================
// Kernel C: out (128->128) via mma.sync bf16 3-term split
// D[o][s] = W2[o][k] * H[s][k]^T ; A=W2 row-major, B=H row-major (col frag)
// ================================================================
#define OM_TPB  256
// smem byte offsets (A row stride = 136 bf16 = 272 B)
#define OM_BIAS 0           // 128 f32 = 512 B
#define OM_AHI  512         // W2 hi  [128][136] bf16 = 34816
#define OM_ALO  35328       // W2 lo
#define OM_BHI  70144       // H  hi  [128][136] bf16
#define OM_BLO  104960      // H  lo
#define OM_SMEM 139776
// D scratch (f32 [128][132]) overlaps B region
#define OM_D    OM_BHI

#define LDSM_X4(r0, r1, r2, r3, addr) \
    asm volatile("ldmatrix.sync.aligned.m8n8.x4.shared.b16 {%0,%1,%2,%3}, [%4];" \
        : "=r"(r0), "=r"(r1), "=r"(r2), "=r"(r3) : "r"(addr))

#define MMA_BF16(c, a, b0, b1) \
    asm volatile("mma.sync.aligned.m16n8k16.row.col.f32.bf16.bf16.f32 " \
        "{%0,%1,%2,%3}, {%4,%5,%6,%7}, {%8,%9}, {%0,%1,%2,%3};" \
        : "+f"((c)[0]), "+f"((c)[1]), "+f"((c)[2]), "+f"((c)[3]) \
        : "r"((a)[0]), "r"((a)[1]), "r"((a)[2]), "r"((a)[3]), "r"(b0), "r"(b1))

__device__ __forceinline__ uint32_t smem_u32(const void* p) {
    uint32_t a;
    asm("{ .reg .u64 t; cvta.to.shared.u64 t, %1; cvt.u32.u64 %0, t; }" : "=r"(a) : "l"(p));
    return a;
}
// split float2 -> packed bf16x2 hi word + lo(residual) word
__device__ __forceinline__ void bf16split(float f0, float f1, unsigned& hi, unsigned& lo) {
    asm("cvt.rn.bf16x2.f32 %0, %1, %2;" : "=r"(hi) : "f"(f1), "f"(f0));
    const float h0 = __uint_as_float(hi << 16);
    const float h1 = __uint_as_float(hi & 0xFFFF0000u);
    const float r0 = f0 - h0, r1 = f1 - h1;
    asm("cvt.rn.bf16x2.f32 %0, %1, %2;" : "=r"(lo) : "f"(r1), "f"(r0));
}

__global__ void __launch_bounds__(OM_TPB)
out_mma_kernel(const float* __restrict__ w2, const float* __restrict__ b2,
               float* __restrict__ out, int nsamp, int ntiles)
{
    extern __shared__ char smem[];
    const uint32_t sb = smem_u32(smem);
    const int tid = threadIdx.x;
    const int wid = tid >> 5, lid = tid & 31;

    // ---- stage bias + A = W2 (hi/lo) once per block ----
    if (tid < 128) ((float*)(smem + OM_BIAS))[tid] = b2[tid];
    {
        const int o  = tid & 127;
        const int kh = (tid >> 7) * 64;
        const float* wr = w2 + o * 128 + kh;
        char* ah = smem + OM_AHI + o * 272 + kh * 2;
        char* al = smem + OM_ALO + o * 272 + kh * 2;
        for (int i = 0; i < 64; i += 4) {
            const float4 f = *(const float4*)(wr + i);
            unsigned h0, l0, h1, l1;
            bf16split(f.x, f.y, h0, l0);
            bf16split(f.z, f.w, h1, l1);
            *(uint2*)(ah + i * 2) = make_uint2(h0, h1);
            *(uint2*)(al + i * 2) = make_uint2(l0, l1);
        }
    }

    // warp tile assignment: m (outputs) 32 rows, n (samples) 64 cols
    const int mbase0 = (wid & 3) * 32;   // 2 m-tiles: mbase0, mbase0+16
    const int nbase  = (wid >> 2) * 64;  // 8 n-tiles of 8

    for (int tile = blockIdx.x; tile < ntiles; tile += gridDim.x) {
        const long long tbase = (long long)tile * 128;

        __syncthreads();   // previous epilogue reads of D scratch done

        // ---- stage B = H tile (hi/lo) ----
        {
            const int s  = tid & 127;
            const int oh = (tid >> 7) * 64;
            const float* gp = g_h + (tbase + s) * 128 + oh;
            char* bh = smem + OM_BHI + s * 272 + oh * 2;
            char* bl = smem + OM_BLO + s * 272 + oh * 2;
            for (int i = 0; i < 64; i += 4) {
                const float4 f = *(const float4*)(gp + i);
                unsigned h0, l0, h1, l1;
                bf16split(f.x, f.y, h0, l0);
                bf16split(f.z, f.w, h1, l1);
                *(uint2*)(bh + i * 2) = make_uint2(h0, h1);
                *(uint2*)(bl + i * 2) = make_uint2(l0, l1);
            }
        }
        __syncthreads();

        // ---- mma mainloop ----
        float acc[2][8][4];
#pragma unroll
        for (int mt = 0; mt < 2; mt++)
#pragma unroll
            for (int nt = 0; nt < 8; nt++)
#pragma unroll
                for (int q = 0; q < 4; q++) acc[mt][nt][q] = 0.0f;

#pragma unroll
        for (int k0 = 0; k0 < 128; k0 += 16) {
            // A frags: row = mbase + (l&7) + 8*((l>>3)&1), col = k0 + 8*(l>>4)
            uint32_t ahi[2][4], alo[2][4];
            const uint32_t ar = (uint32_t)((lid & 7) + 8 * ((lid >> 3) & 1));
            const uint32_t ac = (uint32_t)(k0 + 8 * (lid >> 4));
#pragma unroll
            for (int mt = 0; mt < 2; mt++) {
                const uint32_t row = mbase0 + mt * 16 + ar;
                const uint32_t off = row * 272 + ac * 2;
                LDSM_X4(ahi[mt][0], ahi[mt][1], ahi[mt][2], ahi[mt][3], sb + OM_AHI + off);
                LDSM_X4(alo[mt][0], alo[mt][1], alo[mt][2], alo[mt][3], sb + OM_ALO + off);
            }
            // B frags: row = nbase + np*16 + (l&7) + 8*(l>>4), col = k0 + 8*((l>>3)&1)
            const uint32_t br = (uint32_t)((lid & 7) + 8 * (lid >> 4));
            const uint32_t bc = (uint32_t)(k0 + 8 * ((lid >> 3) & 1));
#pragma unroll
            for (int np = 0; np < 4; np++) {
                const uint32_t row = nbase + np * 16 + br;
                const uint32_t off = row * 272 + bc * 2;
                uint32_t bh[4], bl[4];
                LDSM_X4(bh[0], bh[1], bh[2], bh[3], sb + OM_BHI + off);
                LDSM_X4(bl[0], bl[1], bl[2], bl[3], sb + OM_BLO + off);
#pragma unroll
                for (int mt = 0; mt < 2; mt++) {
                    MMA_BF16(acc[mt][2 * np],     ahi[mt], bh[0], bh[1]);
                    MMA_BF16(acc[mt][2 * np],     ahi[mt], bl[0], bl[1]);
                    MMA_BF16(acc[mt][2 * np],     alo[mt], bh[0], bh[1]);
                    MMA_BF16(acc[mt][2 * np + 1], ahi[mt], bh[2], bh[3]);
                    MMA_BF16(acc[mt][2 * np + 1], ahi[mt], bl[2], bl[3]);
                    MMA_BF16(acc[mt][2 * np + 1], alo[mt], bh[2], bh[3]);
                }
            }
        }
        __syncthreads();   // all warps done reading B before D scratch overwrite

        // ---- write D frags to smem scratch Dsm[s][o] (stride 132) ----
        {
            float* Dsm = (float*)(smem + OM_D);
            const int mo = lid >> 2;
            const int no = 2 * (lid & 3);
#pragma unroll
            for (int mt = 0; mt < 2; mt++) {
#pragma unroll
                for (int nt = 0; nt < 8; nt++) {
                    const int m = mbase0 + mt * 16 + mo;
                    const int n = nbase + nt * 8 + no;
                    Dsm[n * 132 + m]           = acc[mt][nt][0];
                    Dsm[(n + 1) * 132 + m]     = acc[mt][nt][1];
                    Dsm[n * 132 + m + 8]       = acc[mt][nt][2];
                    Dsm[(n + 1) * 132 + m + 8] = acc[mt][nt][3];
                }
            }
        }
        __syncthreads();

        // ---- coalesced epilogue: out[s][o] = Dsm[s][o] + bias[o] ----
        {
            const float* Dsm = (const float*)(smem + OM_D);
            const float* bp  = (const float*)(smem + OM_BIAS);
            const int s  = tid & 127;
            const int oh = (tid >> 7) * 64;
            const long long gs = tbase + s;
            if (gs < nsamp) {
                float* op = out + gs * 128 + oh;
                const float* dp = Dsm + s * 132 + oh;
#pragma unroll
                for (int i = 0; i < 64; i += 4) {
                    float4 v = *(const float4*)(dp + i);
                    v.x += bp[oh + i];     v.y += bp[oh + i + 1];
                    v.z += bp[oh + i + 2]; v.w += bp[oh + i + 3];
                    *(float4*)(op + i) = v;
                }
            }
        }
    }
}

extern "C" void kernel_launch(void* const* d_in, const int* in_sizes, int n_in,
                              void* d_out, int out_size)
{
    const float* x   = (const float*)d_in[0];
    const float* c1w = (const float*)d_in[1];
    const float* c1b = (const float*)d_in[2];
    const float* c2w = (const float*)d_in[3];
    const float* c2b = (const float*)d_in[4];
    const float* w1  = (const float*)d_in[5];
    const float* b1  = (const float*)d_in[6];
    const float* w2  = (const float*)d_in[7];
    const float* b2  = (const float*)d_in[8];
    float* out = (float*)d_out;

    const int nsamp = in_sizes[0] / 128;

    cudaFuncSetAttribute(fc1_kernel,     cudaFuncAttributeMaxDynamicSharedMemorySize, B_SM_BYTES);
    cudaFuncSetAttribute(out_mma_kernel, cudaFuncAttributeMaxDynamicSharedMemorySize, OM_SMEM);

    conv1_kernel<<<(nsamp + A1TPB - 1) / A1TPB, A1TPB>>>(x, c1w, c1b, nsamp);
    conv2_kernel<<<(nsamp + A2TPB - 1) / A2TPB, A2TPB>>>(c2w, c2b, nsamp);

    const int gblocks = (nsamp + 255) / 256;
    fc1_kernel<<<gblocks, BTPB, B_SM_BYTES>>>(w1, b1, nsamp);

    const int ntiles = (nsamp + 127) / 128;
    const int oblocks = (ntiles < 148) ? ntiles : 148;
    out_mma_kernel<<<oblocks, OM_TPB, OM_SMEM>>>(w2, b2, out, nsamp, ntiles);
}

// round 11
// speedup vs baseline: 2.8701x; 1.1407x over previous
#include <cuda_runtime.h>
#include <cuda_bf16.h>
#include <cstdint>

typedef unsigned long long u64;

#define NSMAX 131072
__device__ float g_c1[108 * NSMAX];   // conv1+pool output [ch*36+y*6+x][sample]
__device__ float g_p2[54 * NSMAX];    // conv2+pool output [k][sample]

__device__ __forceinline__ u64 dup2(float a) {
    u64 r; asm("mov.b64 %0, {%1, %1};" : "=l"(r) : "r"(__float_as_uint(a))); return r;
}
__device__ __forceinline__ u64 pack2(float lo, float hi) {
    u64 r; asm("mov.b64 %0, {%1, %2};" : "=l"(r) : "r"(__float_as_uint(lo)), "r"(__float_as_uint(hi))); return r;
}
__device__ __forceinline__ void fma2(u64& acc, u64 a, u64 b) {
    asm("fma.rn.f32x2 %0, %1, %2, %0;" : "+l"(acc) : "l"(a), "l"(b));
}
__device__ __forceinline__ float2 unpack2(u64 v) {
    unsigned lo, hi; asm("mov.b64 {%0, %1}, %2;" : "=r"(lo), "=r"(hi) : "l"(v));
    return make_float2(__uint_as_float(lo), __uint_as_float(hi));
}

// ================================================================
// Kernel A1: conv1 (1->3, 3x3 pad1, 12x12) + maxpool2 + relu -> g_c1
// ================================================================
#define A1TPB 256
__global__ void __launch_bounds__(A1TPB)
conv1_kernel(const float* __restrict__ x,
             const float* __restrict__ c1w, const float* __restrict__ c1b, int nsamp)
{
    __shared__ float ws[32];
    const int tid = threadIdx.x;
    if (tid < 27) ws[tid] = c1w[tid];
    if (tid < 3)  ws[27 + tid] = c1b[tid];
    __syncthreads();

    const long long s = (long long)blockIdx.x * A1TPB + tid;
    if (s >= nsamp) return;
    const float* xp = x + s * 128;

    float W[27];
#pragma unroll
    for (int i = 0; i < 27; i++) W[i] = ws[i];
    const float B0 = ws[27], B1 = ws[28], B2 = ws[29];

#pragma unroll
    for (int py = 0; py < 6; py++) {
        float r[4][12];
#pragma unroll
        for (int j = 0; j < 4; j++) {
            const int rr = 2 * py - 1 + j;
            if (rr < 0 || rr >= 11) {
#pragma unroll
                for (int c = 0; c < 12; c++) r[j][c] = 0.0f;
            } else if (rr == 10) {
#pragma unroll
                for (int c = 0; c < 8; c += 2) {
                    float2 v = *(const float2*)(xp + 120 + c);
                    r[j][c] = v.x; r[j][c + 1] = v.y;
                }
                r[j][8] = 0.0f; r[j][9] = 0.0f; r[j][10] = 0.0f; r[j][11] = 0.0f;
            } else {
#pragma unroll
                for (int c = 0; c < 12; c += 2) {
                    float2 v = *(const float2*)(xp + 12 * rr + c);
                    r[j][c] = v.x; r[j][c + 1] = v.y;
                }
            }
        }
#pragma unroll
        for (int oc = 0; oc < 3; oc++) {
            float v0[12], v1[12];
#pragma unroll
            for (int cx = 0; cx < 12; cx++) {
                float a0 = 0.0f, a1 = 0.0f;
#pragma unroll
                for (int ky = 0; ky < 3; ky++) {
#pragma unroll
                    for (int kx = 0; kx < 3; kx++) {
                        const int col = cx + kx - 1;
                        if (col >= 0 && col < 12) {
                            const float w = W[oc * 9 + ky * 3 + kx];
                            a0 = fmaf(w, r[ky][col],     a0);
                            a1 = fmaf(w, r[ky + 1][col], a1);
                        }
                    }
                }
                v0[cx] = a0; v1[cx] = a1;
            }
            const float bb = (oc == 0) ? B0 : ((oc == 1) ? B1 : B2);
#pragma unroll
            for (int px = 0; px < 6; px++) {
                float m = fmaxf(fmaxf(v0[2 * px], v0[2 * px + 1]),
                                fmaxf(v1[2 * px], v1[2 * px + 1]));
                g_c1[(long long)(oc * 36 + py * 6 + px) * NSMAX + s] = fmaxf(m + bb, 0.0f);
            }
        }
    }
}

// ================================================================
// Kernel A2: conv2 (3->6, 3x3 pad1, 6x6) + maxpool2 + relu -> g_p2
// ================================================================
#define A2TPB 256
__global__ void __launch_bounds__(A2TPB)
conv2_kernel(const float* __restrict__ c2w, const float* __restrict__ c2b, int nsamp)
{
    __shared__ float ws[168];
    const int tid = threadIdx.x;
    if (tid < 162) ws[tid] = c2w[tid];
    if (tid < 6)   ws[162 + tid] = c2b[tid];
    __syncthreads();

    const long long s = (long long)blockIdx.x * A2TPB + tid;
    if (s >= nsamp) return;

#pragma unroll
    for (int py = 0; py < 3; py++) {
#pragma unroll
        for (int oh = 0; oh < 2; oh++) {
            u64 acc[3][3][2];
#pragma unroll
            for (int q = 0; q < 3; q++)
#pragma unroll
                for (int px = 0; px < 3; px++) { acc[q][px][0] = 0ull; acc[q][px][1] = 0ull; }

#pragma unroll
            for (int ic = 0; ic < 3; ic++) {
                float rw[4][6];
#pragma unroll
                for (int j = 0; j < 4; j++) {
                    const int y = 2 * py - 1 + j;
                    if (y < 0 || y > 5) {
#pragma unroll
                        for (int ix = 0; ix < 6; ix++) rw[j][ix] = 0.0f;
                    } else {
#pragma unroll
                        for (int ix = 0; ix < 6; ix++)
                            rw[j][ix] = g_c1[(long long)(ic * 36 + y * 6 + ix) * NSMAX + s];
                    }
                }
                u64 pc[3][6];
#pragma unroll
                for (int j = 0; j < 3; j++)
#pragma unroll
                    for (int ix = 0; ix < 6; ix++)
                        pc[j][ix] = pack2(rw[j][ix], rw[j + 1][ix]);

#pragma unroll
                for (int q = 0; q < 3; q++) {
                    const int oc = oh * 3 + q;
#pragma unroll
                    for (int ky = 0; ky < 3; ky++) {
#pragma unroll
                        for (int kx = 0; kx < 3; kx++) {
                            const u64 wd = dup2(ws[oc * 27 + ic * 9 + ky * 3 + kx]);
#pragma unroll
                            for (int px = 0; px < 3; px++) {
                                const int ix0 = 2 * px + kx - 1;
                                const int ix1 = 2 * px + kx;
                                if (ix0 >= 0 && ix0 < 6) fma2(acc[q][px][0], wd, pc[ky][ix0]);
                                if (ix1 < 6)             fma2(acc[q][px][1], wd, pc[ky][ix1]);
                            }
                        }
                    }
                }
            }
#pragma unroll
            for (int q = 0; q < 3; q++) {
                const int oc = oh * 3 + q;
                const float bb = ws[162 + oc];
#pragma unroll
                for (int px = 0; px < 3; px++) {
                    float2 v0 = unpack2(acc[q][px][0]), v1 = unpack2(acc[q][px][1]);
                    float m = fmaxf(fmaxf(v0.x, v0.y), fmaxf(v1.x, v1.y));
                    g_p2[(long long)(oc * 9 + py * 3 + px) * NSMAX + s] = fmaxf(m + bb, 0.0f);
                }
            }
        }
    }
}

// ================================================================
// Kernel F: fused fc1+relu+out via chained mma.sync bf16 3-term split
//   GEMM1: H[o1][s]  = relu(W1[o1][k54] * P2[s][k54]^T + b1)
//   GEMM2: out[o2][s] = W2[o2][k=o1] * H[s][k]^T + b2
// 512 threads; warp grid 4(m) x 4(n); warp tile m32 x n32; persistent blocks
// ================================================================
#define FK_TPB  512
// smem byte offsets
#define F_B1   0          // 128 f32
#define F_B2   512        // 128 f32
#define F_W1H  1024       // [128][72] bf16 = 18432
#define F_W1L  19456
#define F_W2H  37888      // [128][136] bf16 = 34816
#define F_W2L  72704
#define F_P2H  107520     // [128][72] bf16
#define F_P2L  125952
#define F_HH   144384     // [128][136] bf16
#define F_HL   179200
#define F_D    144384     // f32 [128][132] = 67584, overlaps H region
#define FK_SMEM 214016

#define LDSM_X4(r0, r1, r2, r3, addr) \
    asm volatile("ldmatrix.sync.aligned.m8n8.x4.shared.b16 {%0,%1,%2,%3}, [%4];" \
        : "=r"(r0), "=r"(r1), "=r"(r2), "=r"(r3) : "r"(addr))

#define MMA_BF16(c, a, b0, b1) \
    asm volatile("mma.sync.aligned.m16n8k16.row.col.f32.bf16.bf16.f32 " \
        "{%0,%1,%2,%3}, {%4,%5,%6,%7}, {%8,%9}, {%0,%1,%2,%3};" \
        : "+f"((c)[0]), "+f"((c)[1]), "+f"((c)[2]), "+f"((c)[3]) \
        : "r"((a)[0]), "r"((a)[1]), "r"((a)[2]), "r"((a)[3]), "r"(b0), "r"(b1))

__device__ __forceinline__ uint32_t smem_u32(const void* p) {
    uint32_t a;
    asm("{ .reg .u64 t; cvta.to.shared.u64 t, %1; cvt.u32.u64 %0, t; }" : "=r"(a) : "l"(p));
    return a;
}
__device__ __forceinline__ void bf16split(float f0, float f1, unsigned& hi, unsigned& lo) {
    asm("cvt.rn.bf16x2.f32 %0, %1, %2;" : "=r"(hi) : "f"(f1), "f"(f0));
    const float h0 = __uint_as_float(hi << 16);
    const float h1 = __uint_as_float(hi & 0xFFFF0000u);
    const float r0 = f0 - h0, r1 = f1 - h1;
    asm("cvt.rn.bf16x2.f32 %0, %1, %2;" : "=r"(lo) : "f"(r1), "f"(r0));
}
__device__ __forceinline__ void bf16split1(float v, unsigned short& hi, unsigned short& lo) {
    __nv_bfloat16 h = __float2bfloat16(v);
    float r = v - __bfloat162float(h);
    __nv_bfloat16 l = __float2bfloat16(r);
    hi = *(unsigned short*)&h;
    lo = *(unsigned short*)&l;
}

__global__ void __launch_bounds__(FK_TPB, 1)
head_kernel(const float* __restrict__ w1, const float* __restrict__ b1,
            const float* __restrict__ w2, const float* __restrict__ b2,
            float* __restrict__ out, int nsamp, int ntiles)
{
    extern __shared__ char smem[];
    const uint32_t sb = smem_u32(smem);
    const int tid = threadIdx.x;
    const int wid = tid >> 5, lid = tid & 31;

    // ---- one-time staging ----
    if (tid < 128) { ((float*)(smem + F_B1))[tid] = b1[tid];
                     ((float*)(smem + F_B2))[tid] = b2[tid]; }
    // zero W1/P2 regions (covers the k=54..63 pads that MMA reads)
    for (int i = tid; i < (18432 * 4) / 4; i += FK_TPB)
        ((uint32_t*)(smem + F_W1H))[i] = 0u;        // W1H,W1L are contiguous? no: zero each
    for (int i = tid; i < 18432 / 4; i += FK_TPB) {
        ((uint32_t*)(smem + F_P2H))[i] = 0u;
        ((uint32_t*)(smem + F_P2L))[i] = 0u;
    }
    __syncthreads();
    // W1 [128][54] row-major -> hi/lo bf16 [o][k], stride 72 bf16 (144 B)
    if (tid < 128) {
        const int o = tid;
        const float* wr = w1 + o * 54;
        char* ah = smem + F_W1H + o * 144;
        char* al = smem + F_W1L + o * 144;
        for (int i = 0; i < 54; i += 2) {
            const float2 f = *(const float2*)(wr + i);
            unsigned h, l;
            bf16split(f.x, f.y, h, l);
            *(unsigned*)(ah + i * 2) = h;
            *(unsigned*)(al + i * 2) = l;
        }
    }
    // W2 [128][128] -> hi/lo bf16 [o][k], stride 136 bf16 (272 B)
    {
        const int o  = tid & 127;
        const int kq = (tid >> 7) * 32;
        const float* wr = w2 + o * 128 + kq;
        char* ah = smem + F_W2H + o * 272 + kq * 2;
        char* al = smem + F_W2L + o * 272 + kq * 2;
        for (int i = 0; i < 32; i += 4) {
            const float4 f = *(const float4*)(wr + i);
            unsigned h0, l0, h1, l1;
            bf16split(f.x, f.y, h0, l0);
            bf16split(f.z, f.w, h1, l1);
            *(uint2*)(ah + i * 2) = make_uint2(h0, h1);
            *(uint2*)(al + i * 2) = make_uint2(l0, l1);
        }
    }

    const int mgrp = wid & 3;            // m warp group
    const int ngrp = wid >> 2;           // n warp group
    const int mbase0 = mgrp * 32;
    const int nbase  = ngrp * 32;
    const uint32_t ar = (uint32_t)((lid & 7) + 8 * ((lid >> 3) & 1));
    const uint32_t bq = (uint32_t)((lid & 7) + 8 * (lid >> 4));
    const int mo = lid >> 2;
    const int no = 2 * (lid & 3);

    for (int tile = blockIdx.x; tile < ntiles; tile += gridDim.x) {
        const long long tbase = (long long)tile * 128;

        __syncthreads();   // prior tile's D reads / P2 reads complete

        // ---- stage P2 tile: g_p2[k][s] -> smem [s][k] hi/lo (transpose) ----
        for (int idx = tid; idx < 54 * 32; idx += FK_TPB) {
            const int k = idx >> 5, s4 = (idx & 31) * 4;
            const float4 f = *(const float4*)(g_p2 + (long long)k * NSMAX + tbase + s4);
            unsigned short h, l;
#pragma unroll
            for (int j = 0; j < 4; j++) {
                const float v = (j == 0) ? f.x : (j == 1) ? f.y : (j == 2) ? f.z : f.w;
                bf16split1(v, h, l);
                *(unsigned short*)(smem + F_P2H + (s4 + j) * 144 + k * 2) = h;
                *(unsigned short*)(smem + F_P2L + (s4 + j) * 144 + k * 2) = l;
            }
        }
        __syncthreads();

        // ---- GEMM1: acc1[mt][nt] = W1 * P2^T (K=64, 3-term split) ----
        float acc1[2][4][4];
#pragma unroll
        for (int mt = 0; mt < 2; mt++)
#pragma unroll
            for (int nt = 0; nt < 4; nt++)
#pragma unroll
                for (int q = 0; q < 4; q++) acc1[mt][nt][q] = 0.0f;

#pragma unroll
        for (int k0 = 0; k0 < 64; k0 += 16) {
            const uint32_t ac = (uint32_t)(k0 + 8 * (lid >> 4));
            uint32_t ahi[2][4], alo[2][4];
#pragma unroll
            for (int mt = 0; mt < 2; mt++) {
                const uint32_t off = (mbase0 + mt * 16 + ar) * 144 + ac * 2;
                LDSM_X4(ahi[mt][0], ahi[mt][1], ahi[mt][2], ahi[mt][3], sb + F_W1H + off);
                LDSM_X4(alo[mt][0], alo[mt][1], alo[mt][2], alo[mt][3], sb + F_W1L + off);
            }
            const uint32_t bc = (uint32_t)(k0 + 8 * ((lid >> 3) & 1));
#pragma unroll
            for (int np = 0; np < 2; np++) {
                const uint32_t off = (nbase + np * 16 + bq) * 144 + bc * 2;
                uint32_t bh[4], bl[4];
                LDSM_X4(bh[0], bh[1], bh[2], bh[3], sb + F_P2H + off);
                LDSM_X4(bl[0], bl[1], bl[2], bl[3], sb + F_P2L + off);
#pragma unroll
                for (int mt = 0; mt < 2; mt++) {
                    MMA_BF16(acc1[mt][2 * np],     ahi[mt], bh[0], bh[1]);
                    MMA_BF16(acc1[mt][2 * np],     ahi[mt], bl[0], bl[1]);
                    MMA_BF16(acc1[mt][2 * np],     alo[mt], bh[0], bh[1]);
                    MMA_BF16(acc1[mt][2 * np + 1], ahi[mt], bh[2], bh[3]);
                    MMA_BF16(acc1[mt][2 * np + 1], ahi[mt], bl[2], bl[3]);
                    MMA_BF16(acc1[mt][2 * np + 1], alo[mt], bh[2], bh[3]);
                }
            }
        }

        // ---- epilogue1: relu(+b1) -> H[s][o] hi/lo bf16 in smem ----
        {
            const float* bp = (const float*)(smem + F_B1);
#pragma unroll
            for (int mt = 0; mt < 2; mt++) {
                const int m = mbase0 + mt * 16 + mo;
                const float bA = bp[m], bB = bp[m + 8];
#pragma unroll
                for (int nt = 0; nt < 4; nt++) {
                    const int n = nbase + nt * 8 + no;
                    const float v0 = fmaxf(acc1[mt][nt][0] + bA, 0.0f);
                    const float v1 = fmaxf(acc1[mt][nt][1] + bA, 0.0f);
                    const float v2 = fmaxf(acc1[mt][nt][2] + bB, 0.0f);
                    const float v3 = fmaxf(acc1[mt][nt][3] + bB, 0.0f);
                    unsigned short h, l;
                    bf16split1(v0, h, l);
                    *(unsigned short*)(smem + F_HH + n * 272 + m * 2) = h;
                    *(unsigned short*)(smem + F_HL + n * 272 + m * 2) = l;
                    bf16split1(v1, h, l);
                    *(unsigned short*)(smem + F_HH + (n + 1) * 272 + m * 2) = h;
                    *(unsigned short*)(smem + F_HL + (n + 1) * 272 + m * 2) = l;
                    bf16split1(v2, h, l);
                    *(unsigned short*)(smem + F_HH + n * 272 + (m + 8) * 2) = h;
                    *(unsigned short*)(smem + F_HL + n * 272 + (m + 8) * 2) = l;
                    bf16split1(v3, h, l);
                    *(unsigned short*)(smem + F_HH + (n + 1) * 272 + (m + 8) * 2) = h;
                    *(unsigned short*)(smem + F_HL + (n + 1) * 272 + (m + 8) * 2) = l;
                }
            }
        }
        __syncthreads();

        // ---- GEMM2: acc2[mt][nt] = W2 * H^T (K=128, 3-term split) ----
        float acc2[2][4][4];
#pragma unroll
        for (int mt = 0; mt < 2; mt++)
#pragma unroll
            for (int nt = 0; nt < 4; nt++)
#pragma unroll
                for (int q = 0; q < 4; q++) acc2[mt][nt][q] = 0.0f;

#pragma unroll
        for (int k0 = 0; k0 < 128; k0 += 16) {
            const uint32_t ac = (uint32_t)(k0 + 8 * (lid >> 4));
            uint32_t ahi[2][4], alo[2][4];
#pragma unroll
            for (int mt = 0; mt < 2; mt++) {
                const uint32_t off = (mbase0 + mt * 16 + ar) * 272 + ac * 2;
                LDSM_X4(ahi[mt][0], ahi[mt][1], ahi[mt][2], ahi[mt][3], sb + F_W2H + off);
                LDSM_X4(alo[mt][0], alo[mt][1], alo[mt][2], alo[mt][3], sb + F_W2L + off);
            }
            const uint32_t bc = (uint32_t)(k0 + 8 * ((lid >> 3) & 1));
#pragma unroll
            for (int np = 0; np < 2; np++) {
                const uint32_t off = (nbase + np * 16 + bq) * 272 + bc * 2;
                uint32_t bh[4], bl[4];
                LDSM_X4(bh[0], bh[1], bh[2], bh[3], sb + F_HH + off);
                LDSM_X4(bl[0], bl[1], bl[2], bl[3], sb + F_HL + off);
#pragma unroll
                for (int mt = 0; mt < 2; mt++) {
                    MMA_BF16(acc2[mt][2 * np],     ahi[mt], bh[0], bh[1]);
                    MMA_BF16(acc2[mt][2 * np],     ahi[mt], bl[0], bl[1]);
                    MMA_BF16(acc2[mt][2 * np],     alo[mt], bh[0], bh[1]);
                    MMA_BF16(acc2[mt][2 * np + 1], ahi[mt], bh[2], bh[3]);
                    MMA_BF16(acc2[mt][2 * np + 1], ahi[mt], bl[2], bl[3]);
                    MMA_BF16(acc2[mt][2 * np + 1], alo[mt], bh[2], bh[3]);
                }
            }
        }
        __syncthreads();   // all warps done reading H before D overwrite

        // ---- write D frags to smem scratch Dsm[s][o] (stride 132) ----
        {
            float* Dsm = (float*)(smem + F_D);
#pragma unroll
            for (int mt = 0; mt < 2; mt++) {
                const int m = mbase0 + mt * 16 + mo;
#pragma unroll
                for (int nt = 0; nt < 4; nt++) {
                    const int n = nbase + nt * 8 + no;
                    Dsm[n * 132 + m]           = acc2[mt][nt][0];
                    Dsm[(n + 1) * 132 + m]     = acc2[mt][nt][1];
                    Dsm[n * 132 + m + 8]       = acc2[mt][nt][2];
                    Dsm[(n + 1) * 132 + m + 8] = acc2[mt][nt][3];
                }
            }
        }
        __syncthreads();

        // ---- coalesced epilogue: out[s][o] = Dsm[s][o] + b2[o] ----
        {
            const float* Dsm = (const float*)(smem + F_D);
            const float* bp  = (const float*)(smem + F_B2);
            const int s  = tid & 127;
            const int oh = (tid >> 7) * 32;
            const long long gs = tbase + s;
            if (gs < nsamp) {
                float* op = out + gs * 128 + oh;
                const float* dp = Dsm + s * 132 + oh;
#pragma unroll
                for (int i = 0; i < 32; i += 4) {
                    float4 v = *(const float4*)(dp + i);
                    v.x += bp[oh + i];     v.y += bp[oh + i + 1];
                    v.z += bp[oh + i + 2]; v.w += bp[oh + i + 3];
                    *(float4*)(op + i) = v;
                }
            }
        }
    }
}

extern "C" void kernel_launch(void* const* d_in, const int* in_sizes, int n_in,
                              void* d_out, int out_size)
{
    const float* x   = (const float*)d_in[0];
    const float* c1w = (const float*)d_in[1];
    const float* c1b = (const float*)d_in[2];
    const float* c2w = (const float*)d_in[3];
    const float* c2b = (const float*)d_in[4];
    const float* w1  = (const float*)d_in[5];
    const float* b1  = (const float*)d_in[6];
    const float* w2  = (const float*)d_in[7];
    const float* b2  = (const float*)d_in[8];
    float* out = (float*)d_out;

    const int nsamp = in_sizes[0] / 128;

    cudaFuncSetAttribute(head_kernel, cudaFuncAttributeMaxDynamicSharedMemorySize, FK_SMEM);

    conv1_kernel<<<(nsamp + A1TPB - 1) / A1TPB, A1TPB>>>(x, c1w, c1b, nsamp);
    conv2_kernel<<<(nsamp + A2TPB - 1) / A2TPB, A2TPB>>>(c2w, c2b, nsamp);

    const int ntiles = (nsamp + 127) / 128;
    const int blocks = (ntiles < 148) ? ntiles : 148;
    head_kernel<<<blocks, FK_TPB, FK_SMEM>>>(w1, b1, w2, b2, out, nsamp, ntiles);
}